// round 10
// baseline (speedup 1.0000x reference)
#include <cuda_runtime.h>
#include <cstdint>
#include <math.h>

// Problem constants
#define BDIM 4
#define CDIM 256
#define LDIM 32768

// Gram split-K
#define NSPLIT 32
#define KCTA   (LDIM / NSPLIT)   // 1024
#define NSTG_GRAM (KCTA / 8)     // 128 k-stages of 8

// ---------------------------------------------------------------------------
// Scratch (static device arrays)
// ---------------------------------------------------------------------------
__device__ float gP[BDIM * NSPLIT * 3 * 128 * 128];  // partial Gram tiles (25MB)
__device__ float gG[BDIM * CDIM * CDIM];             // G = x x^T
__device__ float gH2[BDIM * CDIM * CDIM];            // H2 = W_K * G
__device__ float gAm[BDIM * CDIM * CDIM];            // logits -> softmax
__device__ float gM[BDIM * CDIM * CDIM];             // M = A * W_V

// ---------------------------------------------------------------------------
// mma.sync tf32 (sm_80+ PTX — works under compute_100)
// ---------------------------------------------------------------------------
__device__ __forceinline__ float tf32_hi(float v) {
    uint32_t u;
    asm("cvt.rna.tf32.f32 %0, %1;" : "=r"(u) : "f"(v));
    return __uint_as_float(u);
}

#define MMA_TF32(c, a, b)                                                     \
    asm volatile("mma.sync.aligned.m16n8k8.row.col.f32.tf32.tf32.f32 "        \
                 "{%0,%1,%2,%3}, {%4,%5,%6,%7}, {%8,%9}, {%0,%1,%2,%3};"      \
                 : "+f"((c)[0]), "+f"((c)[1]), "+f"((c)[2]), "+f"((c)[3])     \
                 : "r"((a)[0]), "r"((a)[1]), "r"((a)[2]), "r"((a)[3]),        \
                   "r"((b)[0]), "r"((b)[1]))

// ---------------------------------------------------------------------------
// Phase 1: Gram partials, 3xTF32-equivalent accuracy, DOUBLE-BUFFERED.
// k-stage 8 so two (hi/2, lo) float2 stages fit static smem (40 KB).
// Diag tiles: acc = (hi/2)*hi + hi*lo ; G = acc + acc^T  (2 MMAs, no B tile).
// Off-diag: 3 products, hi = 2*(hi/2).
// grid (3, NSPLIT, BDIM), 256 threads, CTA 128x128, warp 64x32.
// ---------------------------------------------------------------------------
__global__ void __launch_bounds__(256, 2) gram_mma(const float* __restrict__ x) {
    __shared__ float2 As2[2][128][10];
    __shared__ float2 Bs2[2][128][10];

    const int t = blockIdx.x, split = blockIdx.y, b = blockIdx.z;
    const bool diag = (t != 1);
    const int ti = (t == 2) ? 1 : 0;
    const int tj = (t == 0) ? 0 : 1;
    const float* Ab = x + ((size_t)b * CDIM + ti * 128) * LDIM + (size_t)split * KCTA;
    const float* Bb = x + ((size_t)b * CDIM + tj * 128) * LDIM + (size_t)split * KCTA;

    const int tid = threadIdx.x;
    const int warp = tid >> 5, lane = tid & 31;
    const int g = lane >> 2, tg = lane & 3;
    const int m0 = (warp >> 2) * 64, n0 = (warp & 3) * 32;
    const int lrow = tid >> 1, lkq = (tid & 1) * 4;   // one float4 per matrix

    float acc[4][4][4];
#pragma unroll
    for (int i = 0; i < 4; i++)
#pragma unroll
        for (int j = 0; j < 4; j++)
#pragma unroll
            for (int k = 0; k < 4; k++) acc[i][j][k] = 0.f;

    const float* A0 = Ab + (size_t)lrow * LDIM + lkq;
    const float* B0 = Bb + (size_t)lrow * LDIM + lkq;

    float4 va, vb;

#define GRAM_STORE(st)                                                         \
    do {                                                                       \
        _Pragma("unroll") for (int j = 0; j < 4; j++) {                        \
            float v = ((const float*)&va)[j];                                  \
            float h = tf32_hi(v);                                              \
            As2[st][lrow][lkq + j] = make_float2(0.5f * h, v - h);             \
        }                                                                      \
        if (!diag) {                                                           \
            _Pragma("unroll") for (int j = 0; j < 4; j++) {                    \
                float v = ((const float*)&vb)[j];                              \
                float h = tf32_hi(v);                                          \
                Bs2[st][lrow][lkq + j] = make_float2(0.5f * h, v - h);         \
            }                                                                  \
        }                                                                      \
    } while (0)

    // Prologue: stage 0 stored, stage 1 prefetched to regs.
    va = *(const float4*)A0;
    if (!diag) vb = *(const float4*)B0;
    GRAM_STORE(0);
    va = *(const float4*)(A0 + 8);
    if (!diag) vb = *(const float4*)(B0 + 8);
    __syncthreads();

    for (int c = 0; c < NSTG_GRAM; c++) {
        const int p = c & 1;
        if (c + 1 < NSTG_GRAM) {
            GRAM_STORE(p ^ 1);
            if (c + 2 < NSTG_GRAM) {
                va = *(const float4*)(A0 + (c + 2) * 8);
                if (!diag) vb = *(const float4*)(B0 + (c + 2) * 8);
            }
        }
        if (diag) {
            uint32_t af[4][4], bh[4][2], bl[4][2];
#pragma unroll
            for (int mt = 0; mt < 4; mt++) {
                const int r = m0 + mt * 16 + g;
                float2 p0 = As2[p][r][tg];
                float2 p1 = As2[p][r + 8][tg];
                float2 p2 = As2[p][r][tg + 4];
                float2 p3 = As2[p][r + 8][tg + 4];
                af[mt][0] = __float_as_uint(p0.x);   // hi/2
                af[mt][1] = __float_as_uint(p1.x);
                af[mt][2] = __float_as_uint(p2.x);
                af[mt][3] = __float_as_uint(p3.x);
            }
#pragma unroll
            for (int nt = 0; nt < 4; nt++) {
                const int rn = n0 + nt * 8 + g;
                float2 q0 = As2[p][rn][tg];
                float2 q1 = As2[p][rn][tg + 4];
                bh[nt][0] = __float_as_uint(2.f * q0.x);  // hi
                bh[nt][1] = __float_as_uint(2.f * q1.x);
                bl[nt][0] = __float_as_uint(q0.y);        // lo
                bl[nt][1] = __float_as_uint(q1.y);
            }
            // product 1: (hi/2) * hi
#pragma unroll
            for (int mt = 0; mt < 4; mt++)
#pragma unroll
                for (int nt = 0; nt < 4; nt++)
                    MMA_TF32(acc[mt][nt], af[mt], bh[nt]);
            // af <- hi (2 * hi/2, exact)
#pragma unroll
            for (int mt = 0; mt < 4; mt++)
#pragma unroll
                for (int q = 0; q < 4; q++)
                    af[mt][q] = __float_as_uint(2.f * __uint_as_float(af[mt][q]));
            // product 2: hi * lo
#pragma unroll
            for (int mt = 0; mt < 4; mt++)
#pragma unroll
                for (int nt = 0; nt < 4; nt++)
                    MMA_TF32(acc[mt][nt], af[mt], bl[nt]);
        } else {
            uint32_t ah[4][4], al[4][4], bh[4][2], bl[4][2];
#pragma unroll
            for (int mt = 0; mt < 4; mt++) {
                const int r = m0 + mt * 16 + g;
                float2 p0 = As2[p][r][tg];
                float2 p1 = As2[p][r + 8][tg];
                float2 p2 = As2[p][r][tg + 4];
                float2 p3 = As2[p][r + 8][tg + 4];
                ah[mt][0] = __float_as_uint(2.f * p0.x);
                ah[mt][1] = __float_as_uint(2.f * p1.x);
                ah[mt][2] = __float_as_uint(2.f * p2.x);
                ah[mt][3] = __float_as_uint(2.f * p3.x);
                al[mt][0] = __float_as_uint(p0.y);
                al[mt][1] = __float_as_uint(p1.y);
                al[mt][2] = __float_as_uint(p2.y);
                al[mt][3] = __float_as_uint(p3.y);
            }
#pragma unroll
            for (int nt = 0; nt < 4; nt++) {
                const int rn = n0 + nt * 8 + g;
                float2 q0 = Bs2[p][rn][tg];
                float2 q1 = Bs2[p][rn][tg + 4];
                bh[nt][0] = __float_as_uint(2.f * q0.x);
                bh[nt][1] = __float_as_uint(2.f * q1.x);
                bl[nt][0] = __float_as_uint(q0.y);
                bl[nt][1] = __float_as_uint(q1.y);
            }
#pragma unroll
            for (int mt = 0; mt < 4; mt++)
#pragma unroll
                for (int nt = 0; nt < 4; nt++) {
                    MMA_TF32(acc[mt][nt], ah[mt], bh[nt]);
                    MMA_TF32(acc[mt][nt], ah[mt], bl[nt]);
                    MMA_TF32(acc[mt][nt], al[mt], bh[nt]);
                }
        }
        __syncthreads();
    }
#undef GRAM_STORE

    float* Cp = gP + (((size_t)b * NSPLIT + split) * 3 + t) * 16384;
#pragma unroll
    for (int mt = 0; mt < 4; mt++)
#pragma unroll
        for (int nt = 0; nt < 4; nt++) {
            const int r = m0 + mt * 16 + g;
            const int c = n0 + nt * 8 + 2 * tg;
            float2 v0; v0.x = acc[mt][nt][0]; v0.y = acc[mt][nt][1];
            float2 v1; v1.x = acc[mt][nt][2]; v1.y = acc[mt][nt][3];
            *(float2*)(Cp + (size_t)r * 128 + c) = v0;
            *(float2*)(Cp + (size_t)(r + 8) * 128 + c) = v1;
        }
}

// Reduce partials over splits into G. Diag tiles raw (symmetrized next);
// off-diag mirrored.
__global__ void gram_reduce() {
    const int idx = blockIdx.x * 256 + threadIdx.x;   // 0..49151
    const int b = blockIdx.y;
    const int t = idx >> 14;
    const int e = idx & 16383;
    const int i = e >> 7, j = e & 127;
    const float* p = gP + (((size_t)b * NSPLIT) * 3 + t) * 16384 + e;
    float sum = 0.f;
#pragma unroll 8
    for (int s = 0; s < NSPLIT; s++) sum += p[(size_t)s * 3 * 16384];
    float* Gb = gG + (size_t)b * 65536;
    if (t == 0) {
        Gb[(size_t)i * 256 + j] = sum;
    } else if (t == 2) {
        Gb[(size_t)(128 + i) * 256 + (128 + j)] = sum;
    } else {
        Gb[(size_t)i * 256 + (128 + j)] = sum;
        Gb[(size_t)(128 + j) * 256 + i] = sum;
    }
}

// Symmetrize diag blocks in place: G[p][q] = Graw[p][q] + Graw[q][p].
__global__ void sym_diag() {
    const int pu[10] = {0, 0, 0, 0, 1, 1, 1, 2, 2, 3};
    const int pv[10] = {0, 1, 2, 3, 1, 2, 3, 2, 3, 3};
    const int pr = blockIdx.x, dblk = blockIdx.y, b = blockIdx.z;
    const int u = pu[pr], v = pv[pr];
    const int base = dblk * 128;
    float* Gb = gG + (size_t)b * 65536;
    __shared__ float Ta[32][33], Tb[32][33];
    const int r = threadIdx.x >> 3, c4 = (threadIdx.x & 7) * 4;
    const int ar = base + u * 32, ac = base + v * 32;
    const int br = base + v * 32, bc = base + u * 32;
    float4 a = *(const float4*)(Gb + (size_t)(ar + r) * 256 + ac + c4);
    float4 bq = *(const float4*)(Gb + (size_t)(br + r) * 256 + bc + c4);
#pragma unroll
    for (int j = 0; j < 4; j++) {
        Ta[r][c4 + j] = ((const float*)&a)[j];
        Tb[r][c4 + j] = ((const float*)&bq)[j];
    }
    __syncthreads();
    float4 o1, o2;
#pragma unroll
    for (int j = 0; j < 4; j++) {
        ((float*)&o1)[j] = Ta[r][c4 + j] + Tb[c4 + j][r];
        ((float*)&o2)[j] = Tb[r][c4 + j] + Ta[c4 + j][r];
    }
    *(float4*)(Gb + (size_t)(ar + r) * 256 + ac + c4) = o1;
    if (u != v)
        *(float4*)(Gb + (size_t)(br + r) * 256 + bc + c4) = o2;
}

// ---------------------------------------------------------------------------
// 32x64 SGEMM tiles for the middle GEMMs, DOUBLE-BUFFERED (one sync/k-step,
// STS overlaps FFMA). grid 8x4xB = 128 blocks.
// ---------------------------------------------------------------------------
struct Smem3264 {
    float As[2][16][36];
    float Bs[2][16][68];
};

// NT: C[m][n] = sum_k A[m][k] * B[n][k]
__device__ __forceinline__ void gemm_nt_3264(Smem3264& s,
                                             const float* __restrict__ A,
                                             const float* __restrict__ B,
                                             float* __restrict__ C) {
    const int tid = threadIdx.x;
    const int row = tid >> 2, kq = (tid & 3) * 4;
    const int tx = tid & 15, ty = tid >> 4;
    const int n0 = tx * 4, m0 = ty * 2;
    float acc[2][4] = {};
    float4 a, bv;

#define NT_STORE(st)                                                           \
    do {                                                                       \
        if (tid < 128) {                                                       \
            _Pragma("unroll") for (int j = 0; j < 4; j++)                      \
                s.As[st][kq + j][row] = ((const float*)&a)[j];                 \
        }                                                                      \
        _Pragma("unroll") for (int j = 0; j < 4; j++)                          \
            s.Bs[st][kq + j][row] = ((const float*)&bv)[j];                    \
    } while (0)

    if (tid < 128) a = *(const float4*)(A + (size_t)row * 256 + kq);
    bv = *(const float4*)(B + (size_t)row * 256 + kq);
    NT_STORE(0);
    if (tid < 128) a = *(const float4*)(A + (size_t)row * 256 + 16 + kq);
    bv = *(const float4*)(B + (size_t)row * 256 + 16 + kq);
    __syncthreads();

    for (int kt = 0; kt < 16; kt++) {
        const int p = kt & 1;
        if (kt + 1 < 16) {
            NT_STORE(p ^ 1);
            if (kt + 2 < 16) {
                if (tid < 128)
                    a = *(const float4*)(A + (size_t)row * 256 + (kt + 2) * 16 + kq);
                bv = *(const float4*)(B + (size_t)row * 256 + (kt + 2) * 16 + kq);
            }
        }
#pragma unroll
        for (int kk = 0; kk < 16; kk++) {
            const float av0 = s.As[p][kk][m0];
            const float av1 = s.As[p][kk][m0 + 1];
#pragma unroll
            for (int j = 0; j < 4; j++) {
                const float bb = s.Bs[p][kk][n0 + j];
                acc[0][j] += av0 * bb;
                acc[1][j] += av1 * bb;
            }
        }
        __syncthreads();
    }
#undef NT_STORE
#pragma unroll
    for (int i = 0; i < 2; i++) {
        float4 v;
        v.x = acc[i][0]; v.y = acc[i][1]; v.z = acc[i][2]; v.w = acc[i][3];
        *(float4*)(C + (size_t)(m0 + i) * 256 + n0) = v;
    }
}

// NN: C[m][n] = sum_k A[m][k] * B[k][n]  (B row-major [k][n], ldb=256)
__device__ __forceinline__ void gemm_nn_3264(Smem3264& s,
                                             const float* __restrict__ A,
                                             const float* __restrict__ B,
                                             float* __restrict__ C) {
    const int tid = threadIdx.x;
    const int row = tid >> 2, kq = (tid & 3) * 4;
    const int kr = tid >> 4, cq = (tid & 15) * 4;
    const int tx = tid & 15, ty = tid >> 4;
    const int n0 = tx * 4, m0 = ty * 2;
    float acc[2][4] = {};
    float4 a, bv;

#define NN_STORE(st)                                                           \
    do {                                                                       \
        if (tid < 128) {                                                       \
            _Pragma("unroll") for (int j = 0; j < 4; j++)                      \
                s.As[st][kq + j][row] = ((const float*)&a)[j];                 \
        }                                                                      \
        _Pragma("unroll") for (int j = 0; j < 4; j++)                          \
            s.Bs[st][kr][cq + j] = ((const float*)&bv)[j];                     \
    } while (0)

    if (tid < 128) a = *(const float4*)(A + (size_t)row * 256 + kq);
    bv = *(const float4*)(B + (size_t)kr * 256 + cq);
    NN_STORE(0);
    if (tid < 128) a = *(const float4*)(A + (size_t)row * 256 + 16 + kq);
    bv = *(const float4*)(B + (size_t)(16 + kr) * 256 + cq);
    __syncthreads();

    for (int kt = 0; kt < 16; kt++) {
        const int p = kt & 1;
        if (kt + 1 < 16) {
            NN_STORE(p ^ 1);
            if (kt + 2 < 16) {
                if (tid < 128)
                    a = *(const float4*)(A + (size_t)row * 256 + (kt + 2) * 16 + kq);
                bv = *(const float4*)(B + (size_t)((kt + 2) * 16 + kr) * 256 + cq);
            }
        }
#pragma unroll
        for (int kk = 0; kk < 16; kk++) {
            const float av0 = s.As[p][kk][m0];
            const float av1 = s.As[p][kk][m0 + 1];
#pragma unroll
            for (int j = 0; j < 4; j++) {
                const float bb = s.Bs[p][kk][n0 + j];
                acc[0][j] += av0 * bb;
                acc[1][j] += av1 * bb;
            }
        }
        __syncthreads();
    }
#undef NN_STORE
#pragma unroll
    for (int i = 0; i < 2; i++) {
        float4 v;
        v.x = acc[i][0]; v.y = acc[i][1]; v.z = acc[i][2]; v.w = acc[i][3];
        *(float4*)(C + (size_t)(m0 + i) * 256 + n0) = v;
    }
}

__global__ void __launch_bounds__(256) gemm_h2_kernel(const float* __restrict__ wk) {
    __shared__ Smem3264 s;
    const int bx = blockIdx.x, by = blockIdx.y, b = blockIdx.z;
    gemm_nt_3264(s, wk + (size_t)bx * 32 * 256,
                 gG + (size_t)b * 65536 + (size_t)by * 64 * 256,
                 gH2 + (size_t)b * 65536 + (size_t)bx * 32 * 256 + by * 64);
}
__global__ void __launch_bounds__(256) gemm_attn_kernel(const float* __restrict__ wq) {
    __shared__ Smem3264 s;
    const int bx = blockIdx.x, by = blockIdx.y, b = blockIdx.z;
    gemm_nt_3264(s, wq + (size_t)bx * 32 * 256,
                 gH2 + (size_t)b * 65536 + (size_t)by * 64 * 256,
                 gAm + (size_t)b * 65536 + (size_t)bx * 32 * 256 + by * 64);
}
__global__ void __launch_bounds__(256) gemm_m_kernel(const float* __restrict__ wv) {
    __shared__ Smem3264 s;
    const int bx = blockIdx.x, by = blockIdx.y, b = blockIdx.z;
    gemm_nn_3264(s, gAm + (size_t)b * 65536 + (size_t)bx * 32 * 256,
                 wv + by * 64,
                 gM + (size_t)b * 65536 + (size_t)bx * 32 * 256 + by * 64);
}

// ---------------------------------------------------------------------------
// Softmax over q (axis=-2), grid (16, B): 16 cols/block, 16 q per thread.
// ---------------------------------------------------------------------------
__global__ void __launch_bounds__(256) softmax_kernel() {
    const int b = blockIdx.y;
    const int tc = threadIdx.x & 15, tq = threadIdx.x >> 4;
    const int col = blockIdx.x * 16 + tc;
    float* Ab = gAm + (size_t)b * 65536;

    float v[16];
    float m = -3.0e38f;
#pragma unroll
    for (int qi = 0; qi < 16; qi++) {
        v[qi] = Ab[(size_t)(tq + qi * 16) * 256 + col];
        m = fmaxf(m, v[qi]);
    }
    __shared__ float red[16][16];
    red[tq][tc] = m;
    __syncthreads();
    float mm = red[0][tc];
#pragma unroll
    for (int r = 1; r < 16; r++) mm = fmaxf(mm, red[r][tc]);
    __syncthreads();
    float ssum = 0.f;
#pragma unroll
    for (int qi = 0; qi < 16; qi++) {
        v[qi] = expf(v[qi] - mm);
        ssum += v[qi];
    }
    red[tq][tc] = ssum;
    __syncthreads();
    float tot = 0.f;
#pragma unroll
    for (int r = 0; r < 16; r++) tot += red[r][tc];
    const float inv = 1.f / tot;
#pragma unroll
    for (int qi = 0; qi < 16; qi++)
        Ab[(size_t)(tq + qi * 16) * 256 + col] = v[qi] * inv;
}

// ---------------------------------------------------------------------------
// Phase 5: y[b] = M[b] @ x[b] via mma.sync, 1x TF32, 2-stage double buffer.
// ---------------------------------------------------------------------------
__global__ void __launch_bounds__(256, 2) final_mma(const float* __restrict__ x,
                                                    float* __restrict__ y) {
    __shared__ float2 Ap[2][128][10];
    __shared__ float Bs[2][16][136];

    const int lx = blockIdx.x, qy = blockIdx.y, b = blockIdx.z;
    const float* Mb = gM + (size_t)b * 65536 + (size_t)qy * 128 * 256;
    const float* xb = x + (size_t)b * CDIM * LDIM + (size_t)lx * 128;
    float* yb = y + ((size_t)b * CDIM + (size_t)qy * 128) * LDIM + (size_t)lx * 128;

    const int tid = threadIdx.x;
    const int warp = tid >> 5, lane = tid & 31;
    const int g = lane >> 2, tg = lane & 3;
    const int m0 = (warp >> 2) * 64, n0 = (warp & 3) * 32;
    const int lrow = tid >> 2, lkq = (tid & 3) * 4;
    const int brow = tid >> 5, blq = (tid & 31) * 4;
    const int aslot0 = (lkq >= 8) ? 4 : 0;
    const int acomp = ((lkq >> 2) & 1);

    float acc[4][4][4];
#pragma unroll
    for (int i = 0; i < 4; i++)
#pragma unroll
        for (int j = 0; j < 4; j++)
#pragma unroll
            for (int k = 0; k < 4; k++) acc[i][j][k] = 0.f;

    const float* A0 = Mb + (size_t)lrow * 256 + lkq;
    const float* A1 = A0 + (size_t)64 * 256;
    const float* B0 = xb + (size_t)brow * LDIM + blq;
    const float* B1 = B0 + (size_t)8 * LDIM;

#define FIN_STORE(st)                                                          \
    do {                                                                       \
        float* a0p = (float*)&Ap[st][lrow][aslot0];                            \
        float* a1p = (float*)&Ap[st][lrow + 64][aslot0];                       \
        _Pragma("unroll") for (int j = 0; j < 4; j++) {                        \
            a0p[2 * j + acomp] = tf32_hi(((const float*)&va0)[j]);             \
            a1p[2 * j + acomp] = tf32_hi(((const float*)&va1)[j]);             \
            Bs[st][brow][blq + j] = tf32_hi(((const float*)&vb0)[j]);          \
            Bs[st][brow + 8][blq + j] = tf32_hi(((const float*)&vb1)[j]);      \
        }                                                                      \
    } while (0)

    float4 va0 = *(const float4*)A0;
    float4 va1 = *(const float4*)A1;
    float4 vb0 = *(const float4*)B0;
    float4 vb1 = *(const float4*)B1;
    FIN_STORE(0);
    va0 = *(const float4*)(A0 + 16);
    va1 = *(const float4*)(A1 + 16);
    vb0 = *(const float4*)(B0 + (size_t)16 * LDIM);
    vb1 = *(const float4*)(B1 + (size_t)16 * LDIM);
    __syncthreads();

    for (int kt = 0; kt < 16; kt++) {
        const int p = kt & 1;
        if (kt + 1 < 16) {
            FIN_STORE(p ^ 1);
            if (kt + 2 < 16) {
                va0 = *(const float4*)(A0 + (kt + 2) * 16);
                va1 = *(const float4*)(A1 + (kt + 2) * 16);
                vb0 = *(const float4*)(B0 + (size_t)(kt + 2) * 16 * LDIM);
                vb1 = *(const float4*)(B1 + (size_t)(kt + 2) * 16 * LDIM);
            }
        }
#pragma unroll
        for (int s = 0; s < 2; s++) {
            const int k0 = s * 8;
            const int sl = s * 4 + tg;
            uint32_t ah[4][4], bh[4][2];
#pragma unroll
            for (int mt = 0; mt < 4; mt++) {
                const int r = m0 + mt * 16 + g;
                float2 p0 = Ap[p][r][sl];
                float2 p1 = Ap[p][r + 8][sl];
                ah[mt][0] = __float_as_uint(p0.x);
                ah[mt][1] = __float_as_uint(p1.x);
                ah[mt][2] = __float_as_uint(p0.y);
                ah[mt][3] = __float_as_uint(p1.y);
            }
#pragma unroll
            for (int nt = 0; nt < 4; nt++) {
                const int cn = n0 + nt * 8 + g;
                bh[nt][0] = __float_as_uint(Bs[p][k0 + tg][cn]);
                bh[nt][1] = __float_as_uint(Bs[p][k0 + tg + 4][cn]);
            }
#pragma unroll
            for (int mt = 0; mt < 4; mt++)
#pragma unroll
                for (int nt = 0; nt < 4; nt++)
                    MMA_TF32(acc[mt][nt], ah[mt], bh[nt]);
        }
        __syncthreads();
    }
#undef FIN_STORE

#pragma unroll
    for (int mt = 0; mt < 4; mt++)
#pragma unroll
        for (int nt = 0; nt < 4; nt++) {
            const int r = m0 + mt * 16 + g;
            const int c = n0 + nt * 8 + 2 * tg;
            float2 v0; v0.x = acc[mt][nt][0]; v0.y = acc[mt][nt][1];
            float2 v1; v1.x = acc[mt][nt][2]; v1.y = acc[mt][nt][3];
            *(float2*)(yb + (size_t)r * LDIM + c) = v0;
            *(float2*)(yb + (size_t)(r + 8) * LDIM + c) = v1;
        }
}

// ---------------------------------------------------------------------------
// Launch
// ---------------------------------------------------------------------------
extern "C" void kernel_launch(void* const* d_in, const int* in_sizes, int n_in,
                              void* d_out, int out_size) {
    const float *x = nullptr, *wq = nullptr, *wk = nullptr, *wv = nullptr;
    for (int i = 0; i < n_in; i++) {
        if (in_sizes[i] == BDIM * CDIM * LDIM) {
            x = (const float*)d_in[i];
        } else if (!wq) wq = (const float*)d_in[i];
        else if (!wk) wk = (const float*)d_in[i];
        else wv = (const float*)d_in[i];
    }
    float* y = (float*)d_out;

    gram_mma<<<dim3(3, NSPLIT, BDIM), 256>>>(x);
    gram_reduce<<<dim3(192, BDIM), 256>>>();
    sym_diag<<<dim3(10, 2, BDIM), 256>>>();
    gemm_h2_kernel<<<dim3(8, 4, BDIM), 256>>>(wk);
    gemm_attn_kernel<<<dim3(8, 4, BDIM), 256>>>(wq);
    softmax_kernel<<<dim3(16, BDIM), 256>>>();
    gemm_m_kernel<<<dim3(8, 4, BDIM), 256>>>(wv);
    final_mma<<<dim3(LDIM / 128, 2, BDIM), 256>>>(x, y);
}

// round 11
// speedup vs baseline: 1.1163x; 1.1163x over previous
#include <cuda_runtime.h>
#include <cstdint>
#include <math.h>

// Problem constants
#define BDIM 4
#define CDIM 256
#define LDIM 32768

// Gram split-K
#define NSPLIT 32
#define KCTA   (LDIM / NSPLIT)   // 1024
#define NKT_GRAM (KCTA / 16)     // 64 k-stages of 16

// ---------------------------------------------------------------------------
// Scratch (static device arrays)
// ---------------------------------------------------------------------------
__device__ float gP[BDIM * NSPLIT * 3 * 128 * 128];  // partial Gram tiles (25MB)
__device__ float gG[BDIM * CDIM * CDIM];             // G = x x^T
__device__ float gH2[BDIM * CDIM * CDIM];            // H2 = W_K * G
__device__ float gAm[BDIM * CDIM * CDIM];            // logits -> softmax
__device__ float gM[BDIM * CDIM * CDIM];             // M = A * W_V

// ---------------------------------------------------------------------------
// mma.sync tf32 (sm_80+ PTX — works under compute_100)
// ---------------------------------------------------------------------------
__device__ __forceinline__ float tf32_hi(float v) {
    uint32_t u;
    asm("cvt.rna.tf32.f32 %0, %1;" : "=r"(u) : "f"(v));
    return __uint_as_float(u);
}

#define MMA_TF32(c, a, b)                                                     \
    asm volatile("mma.sync.aligned.m16n8k8.row.col.f32.tf32.tf32.f32 "        \
                 "{%0,%1,%2,%3}, {%4,%5,%6,%7}, {%8,%9}, {%0,%1,%2,%3};"      \
                 : "+f"((c)[0]), "+f"((c)[1]), "+f"((c)[2]), "+f"((c)[3])     \
                 : "r"((a)[0]), "r"((a)[1]), "r"((a)[2]), "r"((a)[3]),        \
                   "r"((b)[0]), "r"((b)[1]))

// ---------------------------------------------------------------------------
// Phase 1: Gram partials, 3xTF32-equivalent accuracy.
// k-stage 16 (64 syncs — the R9-proven count), DOUBLE-BUFFERED via 72KB
// dynamic smem: STS of stage p^1 + global prefetch overlap MMAs of stage p.
// Diag tiles (t=0,2): A==B -> acc = (hi/2)*hi + hi*lo, G = acc + acc^T later
// (2 MMA products, no B tile). Off-diag (t=1): 3 products, hi = 2*(hi/2).
// grid (3, NSPLIT, BDIM), 256 threads, CTA 128x128, warp 64x32.
// Layout: float2 stride 18 -> LDS.64 frag loads are 2-way (free for 64-bit).
// ---------------------------------------------------------------------------
#define GRAM_SMEM_BYTES (4 * 128 * 18 * 8)   // 73728

__global__ void __launch_bounds__(256, 2) gram_mma(const float* __restrict__ x) {
    extern __shared__ float2 sm2[];
    float2* Abuf = sm2;                  // [2][128][18]
    float2* Bbuf = sm2 + 2 * 128 * 18;   // [2][128][18]
#define ASM2(st, r, c) Abuf[(st) * 2304 + (r) * 18 + (c)]
#define BSM2(st, r, c) Bbuf[(st) * 2304 + (r) * 18 + (c)]

    const int t = blockIdx.x, split = blockIdx.y, b = blockIdx.z;
    const bool diag = (t != 1);
    const int ti = (t == 2) ? 1 : 0;
    const int tj = (t == 0) ? 0 : 1;
    const float* Ab = x + ((size_t)b * CDIM + ti * 128) * LDIM + (size_t)split * KCTA;
    const float* Bb = x + ((size_t)b * CDIM + tj * 128) * LDIM + (size_t)split * KCTA;

    const int tid = threadIdx.x;
    const int warp = tid >> 5, lane = tid & 31;
    const int g = lane >> 2, tg = lane & 3;
    const int m0 = (warp >> 2) * 64, n0 = (warp & 3) * 32;
    const int lrow = tid >> 2, lkq = (tid & 3) * 4;

    float acc[4][4][4];
#pragma unroll
    for (int i = 0; i < 4; i++)
#pragma unroll
        for (int j = 0; j < 4; j++)
#pragma unroll
            for (int k = 0; k < 4; k++) acc[i][j][k] = 0.f;

    const float* A0 = Ab + (size_t)lrow * LDIM + lkq;
    const float* A1 = A0 + (size_t)64 * LDIM;
    const float* B0 = Bb + (size_t)lrow * LDIM + lkq;
    const float* B1 = B0 + (size_t)64 * LDIM;

    float4 va0, va1, vb0, vb1;

#define GRAM_STORE(st)                                                         \
    do {                                                                       \
        _Pragma("unroll") for (int j = 0; j < 4; j++) {                        \
            float v = ((const float*)&va0)[j];                                 \
            float h = tf32_hi(v);                                              \
            ASM2(st, lrow, lkq + j) = make_float2(0.5f * h, v - h);            \
            v = ((const float*)&va1)[j];                                       \
            h = tf32_hi(v);                                                    \
            ASM2(st, lrow + 64, lkq + j) = make_float2(0.5f * h, v - h);       \
        }                                                                      \
        if (!diag) {                                                           \
            _Pragma("unroll") for (int j = 0; j < 4; j++) {                    \
                float v = ((const float*)&vb0)[j];                             \
                float h = tf32_hi(v);                                          \
                BSM2(st, lrow, lkq + j) = make_float2(0.5f * h, v - h);        \
                v = ((const float*)&vb1)[j];                                   \
                h = tf32_hi(v);                                                \
                BSM2(st, lrow + 64, lkq + j) = make_float2(0.5f * h, v - h);   \
            }                                                                  \
        }                                                                      \
    } while (0)

    // Prologue: stage 0 stored from kt=0; kt=1 prefetched to regs.
    va0 = *(const float4*)A0;
    va1 = *(const float4*)A1;
    if (!diag) { vb0 = *(const float4*)B0; vb1 = *(const float4*)B1; }
    GRAM_STORE(0);
    va0 = *(const float4*)(A0 + 16);
    va1 = *(const float4*)(A1 + 16);
    if (!diag) {
        vb0 = *(const float4*)(B0 + 16);
        vb1 = *(const float4*)(B1 + 16);
    }
    __syncthreads();

    for (int kt = 0; kt < NKT_GRAM; kt++) {
        const int p = kt & 1;
        if (kt + 1 < NKT_GRAM) {
            GRAM_STORE(p ^ 1);
            if (kt + 2 < NKT_GRAM) {
                const int ko = (kt + 2) * 16;
                va0 = *(const float4*)(A0 + ko);
                va1 = *(const float4*)(A1 + ko);
                if (!diag) {
                    vb0 = *(const float4*)(B0 + ko);
                    vb1 = *(const float4*)(B1 + ko);
                }
            }
        }
#pragma unroll
        for (int s = 0; s < 2; s++) {
            const int k0 = s * 8;
            if (diag) {
                uint32_t af[4][4], bh[4][2], bl[4][2];
#pragma unroll
                for (int mt = 0; mt < 4; mt++) {
                    const int r = m0 + mt * 16 + g;
                    float2 p0 = ASM2(p, r, k0 + tg);
                    float2 p1 = ASM2(p, r + 8, k0 + tg);
                    float2 p2 = ASM2(p, r, k0 + tg + 4);
                    float2 p3 = ASM2(p, r + 8, k0 + tg + 4);
                    af[mt][0] = __float_as_uint(p0.x);   // hi/2
                    af[mt][1] = __float_as_uint(p1.x);
                    af[mt][2] = __float_as_uint(p2.x);
                    af[mt][3] = __float_as_uint(p3.x);
                }
#pragma unroll
                for (int nt = 0; nt < 4; nt++) {
                    const int rn = n0 + nt * 8 + g;
                    float2 q0 = ASM2(p, rn, k0 + tg);
                    float2 q1 = ASM2(p, rn, k0 + tg + 4);
                    bh[nt][0] = __float_as_uint(2.f * q0.x);  // hi
                    bh[nt][1] = __float_as_uint(2.f * q1.x);
                    bl[nt][0] = __float_as_uint(q0.y);        // lo
                    bl[nt][1] = __float_as_uint(q1.y);
                }
                // product 1: (hi/2) * hi
#pragma unroll
                for (int mt = 0; mt < 4; mt++)
#pragma unroll
                    for (int nt = 0; nt < 4; nt++)
                        MMA_TF32(acc[mt][nt], af[mt], bh[nt]);
                // af <- hi (2 * hi/2, exact)
#pragma unroll
                for (int mt = 0; mt < 4; mt++)
#pragma unroll
                    for (int q = 0; q < 4; q++)
                        af[mt][q] = __float_as_uint(2.f * __uint_as_float(af[mt][q]));
                // product 2: hi * lo
#pragma unroll
                for (int mt = 0; mt < 4; mt++)
#pragma unroll
                    for (int nt = 0; nt < 4; nt++)
                        MMA_TF32(acc[mt][nt], af[mt], bl[nt]);
            } else {
                uint32_t ah[4][4], al[4][4], bh[4][2], bl[4][2];
#pragma unroll
                for (int mt = 0; mt < 4; mt++) {
                    const int r = m0 + mt * 16 + g;
                    float2 p0 = ASM2(p, r, k0 + tg);
                    float2 p1 = ASM2(p, r + 8, k0 + tg);
                    float2 p2 = ASM2(p, r, k0 + tg + 4);
                    float2 p3 = ASM2(p, r + 8, k0 + tg + 4);
                    ah[mt][0] = __float_as_uint(2.f * p0.x);
                    ah[mt][1] = __float_as_uint(2.f * p1.x);
                    ah[mt][2] = __float_as_uint(2.f * p2.x);
                    ah[mt][3] = __float_as_uint(2.f * p3.x);
                    al[mt][0] = __float_as_uint(p0.y);
                    al[mt][1] = __float_as_uint(p1.y);
                    al[mt][2] = __float_as_uint(p2.y);
                    al[mt][3] = __float_as_uint(p3.y);
                }
#pragma unroll
                for (int nt = 0; nt < 4; nt++) {
                    const int rn = n0 + nt * 8 + g;
                    float2 q0 = BSM2(p, rn, k0 + tg);
                    float2 q1 = BSM2(p, rn, k0 + tg + 4);
                    bh[nt][0] = __float_as_uint(2.f * q0.x);
                    bh[nt][1] = __float_as_uint(2.f * q1.x);
                    bl[nt][0] = __float_as_uint(q0.y);
                    bl[nt][1] = __float_as_uint(q1.y);
                }
#pragma unroll
                for (int mt = 0; mt < 4; mt++)
#pragma unroll
                    for (int nt = 0; nt < 4; nt++) {
                        MMA_TF32(acc[mt][nt], ah[mt], bh[nt]);
                        MMA_TF32(acc[mt][nt], ah[mt], bl[nt]);
                        MMA_TF32(acc[mt][nt], al[mt], bh[nt]);
                    }
            }
        }
        __syncthreads();
    }
#undef GRAM_STORE
#undef ASM2
#undef BSM2

    float* Cp = gP + (((size_t)b * NSPLIT + split) * 3 + t) * 16384;
#pragma unroll
    for (int mt = 0; mt < 4; mt++)
#pragma unroll
        for (int nt = 0; nt < 4; nt++) {
            const int r = m0 + mt * 16 + g;
            const int c = n0 + nt * 8 + 2 * tg;
            float2 v0; v0.x = acc[mt][nt][0]; v0.y = acc[mt][nt][1];
            float2 v1; v1.x = acc[mt][nt][2]; v1.y = acc[mt][nt][3];
            *(float2*)(Cp + (size_t)r * 128 + c) = v0;
            *(float2*)(Cp + (size_t)(r + 8) * 128 + c) = v1;
        }
}

// Reduce partials over splits into G. Diag tiles raw (symmetrized next);
// off-diag mirrored.
__global__ void gram_reduce() {
    const int idx = blockIdx.x * 256 + threadIdx.x;   // 0..49151
    const int b = blockIdx.y;
    const int t = idx >> 14;
    const int e = idx & 16383;
    const int i = e >> 7, j = e & 127;
    const float* p = gP + (((size_t)b * NSPLIT) * 3 + t) * 16384 + e;
    float sum = 0.f;
#pragma unroll 8
    for (int s = 0; s < NSPLIT; s++) sum += p[(size_t)s * 3 * 16384];
    float* Gb = gG + (size_t)b * 65536;
    if (t == 0) {
        Gb[(size_t)i * 256 + j] = sum;
    } else if (t == 2) {
        Gb[(size_t)(128 + i) * 256 + (128 + j)] = sum;
    } else {
        Gb[(size_t)i * 256 + (128 + j)] = sum;
        Gb[(size_t)(128 + j) * 256 + i] = sum;
    }
}

// Symmetrize diag blocks in place: G[p][q] = Graw[p][q] + Graw[q][p].
__global__ void sym_diag() {
    const int pu[10] = {0, 0, 0, 0, 1, 1, 1, 2, 2, 3};
    const int pv[10] = {0, 1, 2, 3, 1, 2, 3, 2, 3, 3};
    const int pr = blockIdx.x, dblk = blockIdx.y, b = blockIdx.z;
    const int u = pu[pr], v = pv[pr];
    const int base = dblk * 128;
    float* Gb = gG + (size_t)b * 65536;
    __shared__ float Ta[32][33], Tb[32][33];
    const int r = threadIdx.x >> 3, c4 = (threadIdx.x & 7) * 4;
    const int ar = base + u * 32, ac = base + v * 32;
    const int br = base + v * 32, bc = base + u * 32;
    float4 a = *(const float4*)(Gb + (size_t)(ar + r) * 256 + ac + c4);
    float4 bq = *(const float4*)(Gb + (size_t)(br + r) * 256 + bc + c4);
#pragma unroll
    for (int j = 0; j < 4; j++) {
        Ta[r][c4 + j] = ((const float*)&a)[j];
        Tb[r][c4 + j] = ((const float*)&bq)[j];
    }
    __syncthreads();
    float4 o1, o2;
#pragma unroll
    for (int j = 0; j < 4; j++) {
        ((float*)&o1)[j] = Ta[r][c4 + j] + Tb[c4 + j][r];
        ((float*)&o2)[j] = Tb[r][c4 + j] + Ta[c4 + j][r];
    }
    *(float4*)(Gb + (size_t)(ar + r) * 256 + ac + c4) = o1;
    if (u != v)
        *(float4*)(Gb + (size_t)(br + r) * 256 + bc + c4) = o2;
}

// ---------------------------------------------------------------------------
// 32x64 SGEMM tiles for the middle GEMMs, DOUBLE-BUFFERED (R10-proven:
// 14.1 -> 13.2 us). grid 8x4xB = 128 blocks.
// ---------------------------------------------------------------------------
struct Smem3264 {
    float As[2][16][36];
    float Bs[2][16][68];
};

// NT: C[m][n] = sum_k A[m][k] * B[n][k]
__device__ __forceinline__ void gemm_nt_3264(Smem3264& s,
                                             const float* __restrict__ A,
                                             const float* __restrict__ B,
                                             float* __restrict__ C) {
    const int tid = threadIdx.x;
    const int row = tid >> 2, kq = (tid & 3) * 4;
    const int tx = tid & 15, ty = tid >> 4;
    const int n0 = tx * 4, m0 = ty * 2;
    float acc[2][4] = {};
    float4 a, bv;

#define NT_STORE(st)                                                           \
    do {                                                                       \
        if (tid < 128) {                                                       \
            _Pragma("unroll") for (int j = 0; j < 4; j++)                      \
                s.As[st][kq + j][row] = ((const float*)&a)[j];                 \
        }                                                                      \
        _Pragma("unroll") for (int j = 0; j < 4; j++)                          \
            s.Bs[st][kq + j][row] = ((const float*)&bv)[j];                    \
    } while (0)

    if (tid < 128) a = *(const float4*)(A + (size_t)row * 256 + kq);
    bv = *(const float4*)(B + (size_t)row * 256 + kq);
    NT_STORE(0);
    if (tid < 128) a = *(const float4*)(A + (size_t)row * 256 + 16 + kq);
    bv = *(const float4*)(B + (size_t)row * 256 + 16 + kq);
    __syncthreads();

    for (int kt = 0; kt < 16; kt++) {
        const int p = kt & 1;
        if (kt + 1 < 16) {
            NT_STORE(p ^ 1);
            if (kt + 2 < 16) {
                if (tid < 128)
                    a = *(const float4*)(A + (size_t)row * 256 + (kt + 2) * 16 + kq);
                bv = *(const float4*)(B + (size_t)row * 256 + (kt + 2) * 16 + kq);
            }
        }
#pragma unroll
        for (int kk = 0; kk < 16; kk++) {
            const float av0 = s.As[p][kk][m0];
            const float av1 = s.As[p][kk][m0 + 1];
#pragma unroll
            for (int j = 0; j < 4; j++) {
                const float bb = s.Bs[p][kk][n0 + j];
                acc[0][j] += av0 * bb;
                acc[1][j] += av1 * bb;
            }
        }
        __syncthreads();
    }
#undef NT_STORE
#pragma unroll
    for (int i = 0; i < 2; i++) {
        float4 v;
        v.x = acc[i][0]; v.y = acc[i][1]; v.z = acc[i][2]; v.w = acc[i][3];
        *(float4*)(C + (size_t)(m0 + i) * 256 + n0) = v;
    }
}

// NN: C[m][n] = sum_k A[m][k] * B[k][n]  (B row-major [k][n], ldb=256)
__device__ __forceinline__ void gemm_nn_3264(Smem3264& s,
                                             const float* __restrict__ A,
                                             const float* __restrict__ B,
                                             float* __restrict__ C) {
    const int tid = threadIdx.x;
    const int row = tid >> 2, kq = (tid & 3) * 4;
    const int kr = tid >> 4, cq = (tid & 15) * 4;
    const int tx = tid & 15, ty = tid >> 4;
    const int n0 = tx * 4, m0 = ty * 2;
    float acc[2][4] = {};
    float4 a, bv;

#define NN_STORE(st)                                                           \
    do {                                                                       \
        if (tid < 128) {                                                       \
            _Pragma("unroll") for (int j = 0; j < 4; j++)                      \
                s.As[st][kq + j][row] = ((const float*)&a)[j];                 \
        }                                                                      \
        _Pragma("unroll") for (int j = 0; j < 4; j++)                          \
            s.Bs[st][kr][cq + j] = ((const float*)&bv)[j];                     \
    } while (0)

    if (tid < 128) a = *(const float4*)(A + (size_t)row * 256 + kq);
    bv = *(const float4*)(B + (size_t)kr * 256 + cq);
    NN_STORE(0);
    if (tid < 128) a = *(const float4*)(A + (size_t)row * 256 + 16 + kq);
    bv = *(const float4*)(B + (size_t)(16 + kr) * 256 + cq);
    __syncthreads();

    for (int kt = 0; kt < 16; kt++) {
        const int p = kt & 1;
        if (kt + 1 < 16) {
            NN_STORE(p ^ 1);
            if (kt + 2 < 16) {
                if (tid < 128)
                    a = *(const float4*)(A + (size_t)row * 256 + (kt + 2) * 16 + kq);
                bv = *(const float4*)(B + (size_t)((kt + 2) * 16 + kr) * 256 + cq);
            }
        }
#pragma unroll
        for (int kk = 0; kk < 16; kk++) {
            const float av0 = s.As[p][kk][m0];
            const float av1 = s.As[p][kk][m0 + 1];
#pragma unroll
            for (int j = 0; j < 4; j++) {
                const float bb = s.Bs[p][kk][n0 + j];
                acc[0][j] += av0 * bb;
                acc[1][j] += av1 * bb;
            }
        }
        __syncthreads();
    }
#undef NN_STORE
#pragma unroll
    for (int i = 0; i < 2; i++) {
        float4 v;
        v.x = acc[i][0]; v.y = acc[i][1]; v.z = acc[i][2]; v.w = acc[i][3];
        *(float4*)(C + (size_t)(m0 + i) * 256 + n0) = v;
    }
}

__global__ void __launch_bounds__(256) gemm_h2_kernel(const float* __restrict__ wk) {
    __shared__ Smem3264 s;
    const int bx = blockIdx.x, by = blockIdx.y, b = blockIdx.z;
    gemm_nt_3264(s, wk + (size_t)bx * 32 * 256,
                 gG + (size_t)b * 65536 + (size_t)by * 64 * 256,
                 gH2 + (size_t)b * 65536 + (size_t)bx * 32 * 256 + by * 64);
}
__global__ void __launch_bounds__(256) gemm_attn_kernel(const float* __restrict__ wq) {
    __shared__ Smem3264 s;
    const int bx = blockIdx.x, by = blockIdx.y, b = blockIdx.z;
    gemm_nt_3264(s, wq + (size_t)bx * 32 * 256,
                 gH2 + (size_t)b * 65536 + (size_t)by * 64 * 256,
                 gAm + (size_t)b * 65536 + (size_t)bx * 32 * 256 + by * 64);
}
__global__ void __launch_bounds__(256) gemm_m_kernel(const float* __restrict__ wv) {
    __shared__ Smem3264 s;
    const int bx = blockIdx.x, by = blockIdx.y, b = blockIdx.z;
    gemm_nn_3264(s, gAm + (size_t)b * 65536 + (size_t)bx * 32 * 256,
                 wv + by * 64,
                 gM + (size_t)b * 65536 + (size_t)bx * 32 * 256 + by * 64);
}

// ---------------------------------------------------------------------------
// Softmax over q (axis=-2), grid (16, B): 16 cols/block, 16 q per thread.
// ---------------------------------------------------------------------------
__global__ void __launch_bounds__(256) softmax_kernel() {
    const int b = blockIdx.y;
    const int tc = threadIdx.x & 15, tq = threadIdx.x >> 4;
    const int col = blockIdx.x * 16 + tc;
    float* Ab = gAm + (size_t)b * 65536;

    float v[16];
    float m = -3.0e38f;
#pragma unroll
    for (int qi = 0; qi < 16; qi++) {
        v[qi] = Ab[(size_t)(tq + qi * 16) * 256 + col];
        m = fmaxf(m, v[qi]);
    }
    __shared__ float red[16][16];
    red[tq][tc] = m;
    __syncthreads();
    float mm = red[0][tc];
#pragma unroll
    for (int r = 1; r < 16; r++) mm = fmaxf(mm, red[r][tc]);
    __syncthreads();
    float ssum = 0.f;
#pragma unroll
    for (int qi = 0; qi < 16; qi++) {
        v[qi] = expf(v[qi] - mm);
        ssum += v[qi];
    }
    red[tq][tc] = ssum;
    __syncthreads();
    float tot = 0.f;
#pragma unroll
    for (int r = 0; r < 16; r++) tot += red[r][tc];
    const float inv = 1.f / tot;
#pragma unroll
    for (int qi = 0; qi < 16; qi++)
        Ab[(size_t)(tq + qi * 16) * 256 + col] = v[qi] * inv;
}

// ---------------------------------------------------------------------------
// Phase 5: y[b] = M[b] @ x[b] via mma.sync, 1x TF32, 2-stage double buffer.
// ---------------------------------------------------------------------------
__global__ void __launch_bounds__(256, 2) final_mma(const float* __restrict__ x,
                                                    float* __restrict__ y) {
    __shared__ float2 Ap[2][128][10];
    __shared__ float Bs[2][16][136];

    const int lx = blockIdx.x, qy = blockIdx.y, b = blockIdx.z;
    const float* Mb = gM + (size_t)b * 65536 + (size_t)qy * 128 * 256;
    const float* xb = x + (size_t)b * CDIM * LDIM + (size_t)lx * 128;
    float* yb = y + ((size_t)b * CDIM + (size_t)qy * 128) * LDIM + (size_t)lx * 128;

    const int tid = threadIdx.x;
    const int warp = tid >> 5, lane = tid & 31;
    const int g = lane >> 2, tg = lane & 3;
    const int m0 = (warp >> 2) * 64, n0 = (warp & 3) * 32;
    const int lrow = tid >> 2, lkq = (tid & 3) * 4;
    const int brow = tid >> 5, blq = (tid & 31) * 4;
    const int aslot0 = (lkq >= 8) ? 4 : 0;
    const int acomp = ((lkq >> 2) & 1);

    float acc[4][4][4];
#pragma unroll
    for (int i = 0; i < 4; i++)
#pragma unroll
        for (int j = 0; j < 4; j++)
#pragma unroll
            for (int k = 0; k < 4; k++) acc[i][j][k] = 0.f;

    const float* A0 = Mb + (size_t)lrow * 256 + lkq;
    const float* A1 = A0 + (size_t)64 * 256;
    const float* B0 = xb + (size_t)brow * LDIM + blq;
    const float* B1 = B0 + (size_t)8 * LDIM;

#define FIN_STORE(st)                                                          \
    do {                                                                       \
        float* a0p = (float*)&Ap[st][lrow][aslot0];                            \
        float* a1p = (float*)&Ap[st][lrow + 64][aslot0];                       \
        _Pragma("unroll") for (int j = 0; j < 4; j++) {                        \
            a0p[2 * j + acomp] = tf32_hi(((const float*)&va0)[j]);             \
            a1p[2 * j + acomp] = tf32_hi(((const float*)&va1)[j]);             \
            Bs[st][brow][blq + j] = tf32_hi(((const float*)&vb0)[j]);          \
            Bs[st][brow + 8][blq + j] = tf32_hi(((const float*)&vb1)[j]);      \
        }                                                                      \
    } while (0)

    float4 va0 = *(const float4*)A0;
    float4 va1 = *(const float4*)A1;
    float4 vb0 = *(const float4*)B0;
    float4 vb1 = *(const float4*)B1;
    FIN_STORE(0);
    va0 = *(const float4*)(A0 + 16);
    va1 = *(const float4*)(A1 + 16);
    vb0 = *(const float4*)(B0 + (size_t)16 * LDIM);
    vb1 = *(const float4*)(B1 + (size_t)16 * LDIM);
    __syncthreads();

    for (int kt = 0; kt < 16; kt++) {
        const int p = kt & 1;
        if (kt + 1 < 16) {
            FIN_STORE(p ^ 1);
            if (kt + 2 < 16) {
                va0 = *(const float4*)(A0 + (kt + 2) * 16);
                va1 = *(const float4*)(A1 + (kt + 2) * 16);
                vb0 = *(const float4*)(B0 + (size_t)(kt + 2) * 16 * LDIM);
                vb1 = *(const float4*)(B1 + (size_t)(kt + 2) * 16 * LDIM);
            }
        }
#pragma unroll
        for (int s = 0; s < 2; s++) {
            const int k0 = s * 8;
            const int sl = s * 4 + tg;
            uint32_t ah[4][4], bh[4][2];
#pragma unroll
            for (int mt = 0; mt < 4; mt++) {
                const int r = m0 + mt * 16 + g;
                float2 p0 = Ap[p][r][sl];
                float2 p1 = Ap[p][r + 8][sl];
                ah[mt][0] = __float_as_uint(p0.x);
                ah[mt][1] = __float_as_uint(p1.x);
                ah[mt][2] = __float_as_uint(p0.y);
                ah[mt][3] = __float_as_uint(p1.y);
            }
#pragma unroll
            for (int nt = 0; nt < 4; nt++) {
                const int cn = n0 + nt * 8 + g;
                bh[nt][0] = __float_as_uint(Bs[p][k0 + tg][cn]);
                bh[nt][1] = __float_as_uint(Bs[p][k0 + tg + 4][cn]);
            }
#pragma unroll
            for (int mt = 0; mt < 4; mt++)
#pragma unroll
                for (int nt = 0; nt < 4; nt++)
                    MMA_TF32(acc[mt][nt], ah[mt], bh[nt]);
        }
        __syncthreads();
    }
#undef FIN_STORE

#pragma unroll
    for (int mt = 0; mt < 4; mt++)
#pragma unroll
        for (int nt = 0; nt < 4; nt++) {
            const int r = m0 + mt * 16 + g;
            const int c = n0 + nt * 8 + 2 * tg;
            float2 v0; v0.x = acc[mt][nt][0]; v0.y = acc[mt][nt][1];
            float2 v1; v1.x = acc[mt][nt][2]; v1.y = acc[mt][nt][3];
            *(float2*)(yb + (size_t)r * LDIM + c) = v0;
            *(float2*)(yb + (size_t)(r + 8) * LDIM + c) = v1;
        }
}

// ---------------------------------------------------------------------------
// Launch
// ---------------------------------------------------------------------------
extern "C" void kernel_launch(void* const* d_in, const int* in_sizes, int n_in,
                              void* d_out, int out_size) {
    const float *x = nullptr, *wq = nullptr, *wk = nullptr, *wv = nullptr;
    for (int i = 0; i < n_in; i++) {
        if (in_sizes[i] == BDIM * CDIM * LDIM) {
            x = (const float*)d_in[i];
        } else if (!wq) wq = (const float*)d_in[i];
        else if (!wk) wk = (const float*)d_in[i];
        else wv = (const float*)d_in[i];
    }
    float* y = (float*)d_out;

    cudaFuncSetAttribute(gram_mma, cudaFuncAttributeMaxDynamicSharedMemorySize,
                         GRAM_SMEM_BYTES);

    gram_mma<<<dim3(3, NSPLIT, BDIM), 256, GRAM_SMEM_BYTES>>>(x);
    gram_reduce<<<dim3(192, BDIM), 256>>>();
    sym_diag<<<dim3(10, 2, BDIM), 256>>>();
    gemm_h2_kernel<<<dim3(8, 4, BDIM), 256>>>(wk);
    gemm_attn_kernel<<<dim3(8, 4, BDIM), 256>>>(wq);
    softmax_kernel<<<dim3(16, BDIM), 256>>>();
    gemm_m_kernel<<<dim3(8, 4, BDIM), 256>>>(wv);
    final_mma<<<dim3(LDIM / 128, 2, BDIM), 256>>>(x, y);
}

// round 12
// speedup vs baseline: 1.4489x; 1.2979x over previous
#include <cuda_runtime.h>
#include <cstdint>
#include <math.h>

// Problem constants
#define BDIM 4
#define CDIM 256
#define LDIM 32768

// Gram split-K
#define NSPLIT 32
#define KCTA   (LDIM / NSPLIT)   // 1024
#define NKT_GRAM (KCTA / 16)     // 64 k-stages of 16

// ---------------------------------------------------------------------------
// Scratch (static device arrays)
// ---------------------------------------------------------------------------
__device__ float gP[BDIM * NSPLIT * 3 * 128 * 128];  // partial Gram tiles (25MB)
__device__ float gG[BDIM * CDIM * CDIM];             // G = x x^T
__device__ float gH2[BDIM * CDIM * CDIM];            // H2 = W_K * G
__device__ float gAm[BDIM * CDIM * CDIM];            // logits -> softmax
__device__ float gM[BDIM * CDIM * CDIM];             // M = A * W_V

// ---------------------------------------------------------------------------
// mma.sync tf32 + bf16 (sm_80+ PTX — works under compute_100)
// ---------------------------------------------------------------------------
__device__ __forceinline__ float tf32_hi(float v) {
    uint32_t u;
    asm("cvt.rna.tf32.f32 %0, %1;" : "=r"(u) : "f"(v));
    return __uint_as_float(u);
}

// pack (v0 -> low half, v1 -> high half) as bf16x2
__device__ __forceinline__ uint32_t bf16pair(float v0, float v1) {
    uint32_t r;
    asm("cvt.rn.bf16x2.f32 %0, %1, %2;" : "=r"(r) : "f"(v1), "f"(v0));
    return r;
}

#define MMA_TF32(c, a, b)                                                     \
    asm volatile("mma.sync.aligned.m16n8k8.row.col.f32.tf32.tf32.f32 "        \
                 "{%0,%1,%2,%3}, {%4,%5,%6,%7}, {%8,%9}, {%0,%1,%2,%3};"      \
                 : "+f"((c)[0]), "+f"((c)[1]), "+f"((c)[2]), "+f"((c)[3])     \
                 : "r"((a)[0]), "r"((a)[1]), "r"((a)[2]), "r"((a)[3]),        \
                   "r"((b)[0]), "r"((b)[1]))

#define MMA_BF16(c, a, b)                                                     \
    asm volatile("mma.sync.aligned.m16n8k16.row.col.f32.bf16.bf16.f32 "       \
                 "{%0,%1,%2,%3}, {%4,%5,%6,%7}, {%8,%9}, {%0,%1,%2,%3};"      \
                 : "+f"((c)[0]), "+f"((c)[1]), "+f"((c)[2]), "+f"((c)[3])     \
                 : "r"((a)[0]), "r"((a)[1]), "r"((a)[2]), "r"((a)[3]),        \
                   "r"((b)[0]), "r"((b)[1]))

// ---------------------------------------------------------------------------
// Phase 1: Gram partials. hi*hi in tf32 (m16n8k8), cross terms hi*lo/lo*hi
// in bf16 (m16n8k16) — corrections are ~2^-11 of G, so bf16's 2^-8 relative
// rounding adds only ~2^-19 overall (invisible under the 1e-3 gate).
// Diag tiles (A==B): acc = (hi/2)*hi [tf32] + hi*lo [bf16]; G = acc + acc^T.
// Off-diag: hi*hi + hi*lo + lo*hi.
// Single smem buffer (R9-proven 64-sync structure):
//   Hs  [128][20] fp32  hi           (frag loads conflict-free)
//   Hp/Lp [128][12] u32 bf16 pairs   (stride 12: all-32-banks-distinct)
// grid (3, NSPLIT, BDIM), 256 threads, CTA 128x128, warp 64x32.
// ---------------------------------------------------------------------------
__global__ void __launch_bounds__(256, 2) gram_mma(const float* __restrict__ x) {
    __shared__ float    HsA[128][20];
    __shared__ uint32_t HpA[128][12], LpA[128][12];
    __shared__ float    HsB[128][20];
    __shared__ uint32_t HpB[128][12], LpB[128][12];

    const int t = blockIdx.x, split = blockIdx.y, b = blockIdx.z;
    const bool diag = (t != 1);
    const int ti = (t == 2) ? 1 : 0;
    const int tj = (t == 0) ? 0 : 1;
    const float* Ab = x + ((size_t)b * CDIM + ti * 128) * LDIM + (size_t)split * KCTA;
    const float* Bb = x + ((size_t)b * CDIM + tj * 128) * LDIM + (size_t)split * KCTA;

    const int tid = threadIdx.x;
    const int warp = tid >> 5, lane = tid & 31;
    const int g = lane >> 2, tg = lane & 3;
    const int m0 = (warp >> 2) * 64, n0 = (warp & 3) * 32;
    const int lrow = tid >> 2, lkq = (tid & 3) * 4;
    const int pk = lkq >> 1;                      // bf16 pair index base

    float acc[4][4][4];
#pragma unroll
    for (int i = 0; i < 4; i++)
#pragma unroll
        for (int j = 0; j < 4; j++)
#pragma unroll
            for (int k = 0; k < 4; k++) acc[i][j][k] = 0.f;

    const float* A0 = Ab + (size_t)lrow * LDIM + lkq;
    const float* A1 = A0 + (size_t)64 * LDIM;
    const float* B0 = Bb + (size_t)lrow * LDIM + lkq;
    const float* B1 = B0 + (size_t)64 * LDIM;

    float4 va0 = *(const float4*)A0;
    float4 va1 = *(const float4*)A1;
    float4 vb0, vb1;
    if (!diag) { vb0 = *(const float4*)B0; vb1 = *(const float4*)B1; }

#define GRAM_STORE_ROW(Hs, Hp, Lp, row, v)                                     \
    do {                                                                       \
        float h0 = tf32_hi((v).x), h1 = tf32_hi((v).y);                        \
        float h2 = tf32_hi((v).z), h3 = tf32_hi((v).w);                        \
        Hs[row][lkq + 0] = h0; Hs[row][lkq + 1] = h1;                          \
        Hs[row][lkq + 2] = h2; Hs[row][lkq + 3] = h3;                          \
        Hp[row][pk]     = bf16pair(h0, h1);                                    \
        Hp[row][pk + 1] = bf16pair(h2, h3);                                    \
        Lp[row][pk]     = bf16pair((v).x - h0, (v).y - h1);                    \
        Lp[row][pk + 1] = bf16pair((v).z - h2, (v).w - h3);                    \
    } while (0)

    for (int kt = 0; kt < NKT_GRAM; kt++) {
        GRAM_STORE_ROW(HsA, HpA, LpA, lrow, va0);
        GRAM_STORE_ROW(HsA, HpA, LpA, lrow + 64, va1);
        if (!diag) {
            GRAM_STORE_ROW(HsB, HpB, LpB, lrow, vb0);
            GRAM_STORE_ROW(HsB, HpB, LpB, lrow + 64, vb1);
        }
        __syncthreads();
        if (kt + 1 < NKT_GRAM) {
            const int ko = (kt + 1) * 16;
            va0 = *(const float4*)(A0 + ko);
            va1 = *(const float4*)(A1 + ko);
            if (!diag) {
                vb0 = *(const float4*)(B0 + ko);
                vb1 = *(const float4*)(B1 + ko);
            }
        }

        // ---- bf16 cross terms (k16, one or two passes) ----
        {
            // pass 1: Ah * Bl^T  (diag: Bl = La)
            uint32_t a16[4][4], b16[4][2];
#pragma unroll
            for (int mt = 0; mt < 4; mt++) {
                const int r = m0 + mt * 16 + g;
                a16[mt][0] = HpA[r][tg];
                a16[mt][1] = HpA[r + 8][tg];
                a16[mt][2] = HpA[r][tg + 4];
                a16[mt][3] = HpA[r + 8][tg + 4];
            }
#pragma unroll
            for (int nt = 0; nt < 4; nt++) {
                const int rn = n0 + nt * 8 + g;
                const uint32_t (*Lsrc)[12] = diag ? LpA : LpB;
                b16[nt][0] = Lsrc[rn][tg];
                b16[nt][1] = Lsrc[rn][tg + 4];
            }
#pragma unroll
            for (int mt = 0; mt < 4; mt++)
#pragma unroll
                for (int nt = 0; nt < 4; nt++)
                    MMA_BF16(acc[mt][nt], a16[mt], b16[nt]);
        }
        if (!diag) {
            // pass 2: Al * Bh^T
            uint32_t a16[4][4], b16[4][2];
#pragma unroll
            for (int mt = 0; mt < 4; mt++) {
                const int r = m0 + mt * 16 + g;
                a16[mt][0] = LpA[r][tg];
                a16[mt][1] = LpA[r + 8][tg];
                a16[mt][2] = LpA[r][tg + 4];
                a16[mt][3] = LpA[r + 8][tg + 4];
            }
#pragma unroll
            for (int nt = 0; nt < 4; nt++) {
                const int rn = n0 + nt * 8 + g;
                b16[nt][0] = HpB[rn][tg];
                b16[nt][1] = HpB[rn][tg + 4];
            }
#pragma unroll
            for (int mt = 0; mt < 4; mt++)
#pragma unroll
                for (int nt = 0; nt < 4; nt++)
                    MMA_BF16(acc[mt][nt], a16[mt], b16[nt]);
        }

        // ---- tf32 hi*hi (k8 x2). Diag: A-side scaled by 0.5 ----
#pragma unroll
        for (int s = 0; s < 2; s++) {
            const int k0 = s * 8;
            uint32_t ah[4][4], bh[4][2];
            const float asc = diag ? 0.5f : 1.0f;
#pragma unroll
            for (int mt = 0; mt < 4; mt++) {
                const int r = m0 + mt * 16 + g;
                ah[mt][0] = __float_as_uint(asc * HsA[r][k0 + tg]);
                ah[mt][1] = __float_as_uint(asc * HsA[r + 8][k0 + tg]);
                ah[mt][2] = __float_as_uint(asc * HsA[r][k0 + tg + 4]);
                ah[mt][3] = __float_as_uint(asc * HsA[r + 8][k0 + tg + 4]);
            }
#pragma unroll
            for (int nt = 0; nt < 4; nt++) {
                const int rn = n0 + nt * 8 + g;
                const float (*Hsrc)[20] = diag ? HsA : HsB;
                bh[nt][0] = __float_as_uint(Hsrc[rn][k0 + tg]);
                bh[nt][1] = __float_as_uint(Hsrc[rn][k0 + tg + 4]);
            }
#pragma unroll
            for (int mt = 0; mt < 4; mt++)
#pragma unroll
                for (int nt = 0; nt < 4; nt++)
                    MMA_TF32(acc[mt][nt], ah[mt], bh[nt]);
        }
        __syncthreads();
    }
#undef GRAM_STORE_ROW

    float* Cp = gP + (((size_t)b * NSPLIT + split) * 3 + t) * 16384;
#pragma unroll
    for (int mt = 0; mt < 4; mt++)
#pragma unroll
        for (int nt = 0; nt < 4; nt++) {
            const int r = m0 + mt * 16 + g;
            const int c = n0 + nt * 8 + 2 * tg;
            float2 v0; v0.x = acc[mt][nt][0]; v0.y = acc[mt][nt][1];
            float2 v1; v1.x = acc[mt][nt][2]; v1.y = acc[mt][nt][3];
            *(float2*)(Cp + (size_t)r * 128 + c) = v0;
            *(float2*)(Cp + (size_t)(r + 8) * 128 + c) = v1;
        }
}

// Reduce partials over splits into G. Diag tiles raw (symmetrized next);
// off-diag mirrored.
__global__ void gram_reduce() {
    const int idx = blockIdx.x * 256 + threadIdx.x;   // 0..49151
    const int b = blockIdx.y;
    const int t = idx >> 14;
    const int e = idx & 16383;
    const int i = e >> 7, j = e & 127;
    const float* p = gP + (((size_t)b * NSPLIT) * 3 + t) * 16384 + e;
    float sum = 0.f;
#pragma unroll 8
    for (int s = 0; s < NSPLIT; s++) sum += p[(size_t)s * 3 * 16384];
    float* Gb = gG + (size_t)b * 65536;
    if (t == 0) {
        Gb[(size_t)i * 256 + j] = sum;
    } else if (t == 2) {
        Gb[(size_t)(128 + i) * 256 + (128 + j)] = sum;
    } else {
        Gb[(size_t)i * 256 + (128 + j)] = sum;
        Gb[(size_t)(128 + j) * 256 + i] = sum;
    }
}

// Symmetrize diag blocks in place: G[p][q] = Graw[p][q] + Graw[q][p].
__global__ void sym_diag() {
    const int pu[10] = {0, 0, 0, 0, 1, 1, 1, 2, 2, 3};
    const int pv[10] = {0, 1, 2, 3, 1, 2, 3, 2, 3, 3};
    const int pr = blockIdx.x, dblk = blockIdx.y, b = blockIdx.z;
    const int u = pu[pr], v = pv[pr];
    const int base = dblk * 128;
    float* Gb = gG + (size_t)b * 65536;
    __shared__ float Ta[32][33], Tb[32][33];
    const int r = threadIdx.x >> 3, c4 = (threadIdx.x & 7) * 4;
    const int ar = base + u * 32, ac = base + v * 32;
    const int br = base + v * 32, bc = base + u * 32;
    float4 a = *(const float4*)(Gb + (size_t)(ar + r) * 256 + ac + c4);
    float4 bq = *(const float4*)(Gb + (size_t)(br + r) * 256 + bc + c4);
#pragma unroll
    for (int j = 0; j < 4; j++) {
        Ta[r][c4 + j] = ((const float*)&a)[j];
        Tb[r][c4 + j] = ((const float*)&bq)[j];
    }
    __syncthreads();
    float4 o1, o2;
#pragma unroll
    for (int j = 0; j < 4; j++) {
        ((float*)&o1)[j] = Ta[r][c4 + j] + Tb[c4 + j][r];
        ((float*)&o2)[j] = Tb[r][c4 + j] + Ta[c4 + j][r];
    }
    *(float4*)(Gb + (size_t)(ar + r) * 256 + ac + c4) = o1;
    if (u != v)
        *(float4*)(Gb + (size_t)(br + r) * 256 + bc + c4) = o2;
}

// ---------------------------------------------------------------------------
// 32x64 SGEMM tiles for the middle GEMMs, DOUBLE-BUFFERED (R10/R11-proven).
// grid 8x4xB = 128 blocks.
// ---------------------------------------------------------------------------
struct Smem3264 {
    float As[2][16][36];
    float Bs[2][16][68];
};

// NT: C[m][n] = sum_k A[m][k] * B[n][k]
__device__ __forceinline__ void gemm_nt_3264(Smem3264& s,
                                             const float* __restrict__ A,
                                             const float* __restrict__ B,
                                             float* __restrict__ C) {
    const int tid = threadIdx.x;
    const int row = tid >> 2, kq = (tid & 3) * 4;
    const int tx = tid & 15, ty = tid >> 4;
    const int n0 = tx * 4, m0 = ty * 2;
    float acc[2][4] = {};
    float4 a, bv;

#define NT_STORE(st)                                                           \
    do {                                                                       \
        if (tid < 128) {                                                       \
            _Pragma("unroll") for (int j = 0; j < 4; j++)                      \
                s.As[st][kq + j][row] = ((const float*)&a)[j];                 \
        }                                                                      \
        _Pragma("unroll") for (int j = 0; j < 4; j++)                          \
            s.Bs[st][kq + j][row] = ((const float*)&bv)[j];                    \
    } while (0)

    if (tid < 128) a = *(const float4*)(A + (size_t)row * 256 + kq);
    bv = *(const float4*)(B + (size_t)row * 256 + kq);
    NT_STORE(0);
    if (tid < 128) a = *(const float4*)(A + (size_t)row * 256 + 16 + kq);
    bv = *(const float4*)(B + (size_t)row * 256 + 16 + kq);
    __syncthreads();

    for (int kt = 0; kt < 16; kt++) {
        const int p = kt & 1;
        if (kt + 1 < 16) {
            NT_STORE(p ^ 1);
            if (kt + 2 < 16) {
                if (tid < 128)
                    a = *(const float4*)(A + (size_t)row * 256 + (kt + 2) * 16 + kq);
                bv = *(const float4*)(B + (size_t)row * 256 + (kt + 2) * 16 + kq);
            }
        }
#pragma unroll
        for (int kk = 0; kk < 16; kk++) {
            const float av0 = s.As[p][kk][m0];
            const float av1 = s.As[p][kk][m0 + 1];
#pragma unroll
            for (int j = 0; j < 4; j++) {
                const float bb = s.Bs[p][kk][n0 + j];
                acc[0][j] += av0 * bb;
                acc[1][j] += av1 * bb;
            }
        }
        __syncthreads();
    }
#undef NT_STORE
#pragma unroll
    for (int i = 0; i < 2; i++) {
        float4 v;
        v.x = acc[i][0]; v.y = acc[i][1]; v.z = acc[i][2]; v.w = acc[i][3];
        *(float4*)(C + (size_t)(m0 + i) * 256 + n0) = v;
    }
}

// NN: C[m][n] = sum_k A[m][k] * B[k][n]  (B row-major [k][n], ldb=256)
__device__ __forceinline__ void gemm_nn_3264(Smem3264& s,
                                             const float* __restrict__ A,
                                             const float* __restrict__ B,
                                             float* __restrict__ C) {
    const int tid = threadIdx.x;
    const int row = tid >> 2, kq = (tid & 3) * 4;
    const int kr = tid >> 4, cq = (tid & 15) * 4;
    const int tx = tid & 15, ty = tid >> 4;
    const int n0 = tx * 4, m0 = ty * 2;
    float acc[2][4] = {};
    float4 a, bv;

#define NN_STORE(st)                                                           \
    do {                                                                       \
        if (tid < 128) {                                                       \
            _Pragma("unroll") for (int j = 0; j < 4; j++)                      \
                s.As[st][kq + j][row] = ((const float*)&a)[j];                 \
        }                                                                      \
        _Pragma("unroll") for (int j = 0; j < 4; j++)                          \
            s.Bs[st][kr][cq + j] = ((const float*)&bv)[j];                     \
    } while (0)

    if (tid < 128) a = *(const float4*)(A + (size_t)row * 256 + kq);
    bv = *(const float4*)(B + (size_t)kr * 256 + cq);
    NN_STORE(0);
    if (tid < 128) a = *(const float4*)(A + (size_t)row * 256 + 16 + kq);
    bv = *(const float4*)(B + (size_t)(16 + kr) * 256 + cq);
    __syncthreads();

    for (int kt = 0; kt < 16; kt++) {
        const int p = kt & 1;
        if (kt + 1 < 16) {
            NN_STORE(p ^ 1);
            if (kt + 2 < 16) {
                if (tid < 128)
                    a = *(const float4*)(A + (size_t)row * 256 + (kt + 2) * 16 + kq);
                bv = *(const float4*)(B + (size_t)((kt + 2) * 16 + kr) * 256 + cq);
            }
        }
#pragma unroll
        for (int kk = 0; kk < 16; kk++) {
            const float av0 = s.As[p][kk][m0];
            const float av1 = s.As[p][kk][m0 + 1];
#pragma unroll
            for (int j = 0; j < 4; j++) {
                const float bb = s.Bs[p][kk][n0 + j];
                acc[0][j] += av0 * bb;
                acc[1][j] += av1 * bb;
            }
        }
        __syncthreads();
    }
#undef NN_STORE
#pragma unroll
    for (int i = 0; i < 2; i++) {
        float4 v;
        v.x = acc[i][0]; v.y = acc[i][1]; v.z = acc[i][2]; v.w = acc[i][3];
        *(float4*)(C + (size_t)(m0 + i) * 256 + n0) = v;
    }
}

__global__ void __launch_bounds__(256) gemm_h2_kernel(const float* __restrict__ wk) {
    __shared__ Smem3264 s;
    const int bx = blockIdx.x, by = blockIdx.y, b = blockIdx.z;
    gemm_nt_3264(s, wk + (size_t)bx * 32 * 256,
                 gG + (size_t)b * 65536 + (size_t)by * 64 * 256,
                 gH2 + (size_t)b * 65536 + (size_t)bx * 32 * 256 + by * 64);
}
__global__ void __launch_bounds__(256) gemm_attn_kernel(const float* __restrict__ wq) {
    __shared__ Smem3264 s;
    const int bx = blockIdx.x, by = blockIdx.y, b = blockIdx.z;
    gemm_nt_3264(s, wq + (size_t)bx * 32 * 256,
                 gH2 + (size_t)b * 65536 + (size_t)by * 64 * 256,
                 gAm + (size_t)b * 65536 + (size_t)bx * 32 * 256 + by * 64);
}
__global__ void __launch_bounds__(256) gemm_m_kernel(const float* __restrict__ wv) {
    __shared__ Smem3264 s;
    const int bx = blockIdx.x, by = blockIdx.y, b = blockIdx.z;
    gemm_nn_3264(s, gAm + (size_t)b * 65536 + (size_t)bx * 32 * 256,
                 wv + by * 64,
                 gM + (size_t)b * 65536 + (size_t)bx * 32 * 256 + by * 64);
}

// ---------------------------------------------------------------------------
// Softmax over q (axis=-2), grid (16, B): 16 cols/block, 16 q per thread.
// ---------------------------------------------------------------------------
__global__ void __launch_bounds__(256) softmax_kernel() {
    const int b = blockIdx.y;
    const int tc = threadIdx.x & 15, tq = threadIdx.x >> 4;
    const int col = blockIdx.x * 16 + tc;
    float* Ab = gAm + (size_t)b * 65536;

    float v[16];
    float m = -3.0e38f;
#pragma unroll
    for (int qi = 0; qi < 16; qi++) {
        v[qi] = Ab[(size_t)(tq + qi * 16) * 256 + col];
        m = fmaxf(m, v[qi]);
    }
    __shared__ float red[16][16];
    red[tq][tc] = m;
    __syncthreads();
    float mm = red[0][tc];
#pragma unroll
    for (int r = 1; r < 16; r++) mm = fmaxf(mm, red[r][tc]);
    __syncthreads();
    float ssum = 0.f;
#pragma unroll
    for (int qi = 0; qi < 16; qi++) {
        v[qi] = expf(v[qi] - mm);
        ssum += v[qi];
    }
    red[tq][tc] = ssum;
    __syncthreads();
    float tot = 0.f;
#pragma unroll
    for (int r = 0; r < 16; r++) tot += red[r][tc];
    const float inv = 1.f / tot;
#pragma unroll
    for (int qi = 0; qi < 16; qi++)
        Ab[(size_t)(tq + qi * 16) * 256 + col] = v[qi] * inv;
}

// ---------------------------------------------------------------------------
// Phase 5: y[b] = M[b] @ x[b] via mma.sync, 1x TF32, 2-stage double buffer.
// ---------------------------------------------------------------------------
__global__ void __launch_bounds__(256, 2) final_mma(const float* __restrict__ x,
                                                    float* __restrict__ y) {
    __shared__ float2 Ap[2][128][10];
    __shared__ float Bs[2][16][136];

    const int lx = blockIdx.x, qy = blockIdx.y, b = blockIdx.z;
    const float* Mb = gM + (size_t)b * 65536 + (size_t)qy * 128 * 256;
    const float* xb = x + (size_t)b * CDIM * LDIM + (size_t)lx * 128;
    float* yb = y + ((size_t)b * CDIM + (size_t)qy * 128) * LDIM + (size_t)lx * 128;

    const int tid = threadIdx.x;
    const int warp = tid >> 5, lane = tid & 31;
    const int g = lane >> 2, tg = lane & 3;
    const int m0 = (warp >> 2) * 64, n0 = (warp & 3) * 32;
    const int lrow = tid >> 2, lkq = (tid & 3) * 4;
    const int brow = tid >> 5, blq = (tid & 31) * 4;
    const int aslot0 = (lkq >= 8) ? 4 : 0;
    const int acomp = ((lkq >> 2) & 1);

    float acc[4][4][4];
#pragma unroll
    for (int i = 0; i < 4; i++)
#pragma unroll
        for (int j = 0; j < 4; j++)
#pragma unroll
            for (int k = 0; k < 4; k++) acc[i][j][k] = 0.f;

    const float* A0 = Mb + (size_t)lrow * 256 + lkq;
    const float* A1 = A0 + (size_t)64 * 256;
    const float* B0 = xb + (size_t)brow * LDIM + blq;
    const float* B1 = B0 + (size_t)8 * LDIM;

#define FIN_STORE(st)                                                          \
    do {                                                                       \
        float* a0p = (float*)&Ap[st][lrow][aslot0];                            \
        float* a1p = (float*)&Ap[st][lrow + 64][aslot0];                       \
        _Pragma("unroll") for (int j = 0; j < 4; j++) {                        \
            a0p[2 * j + acomp] = tf32_hi(((const float*)&va0)[j]);             \
            a1p[2 * j + acomp] = tf32_hi(((const float*)&va1)[j]);             \
            Bs[st][brow][blq + j] = tf32_hi(((const float*)&vb0)[j]);          \
            Bs[st][brow + 8][blq + j] = tf32_hi(((const float*)&vb1)[j]);      \
        }                                                                      \
    } while (0)

    float4 va0 = *(const float4*)A0;
    float4 va1 = *(const float4*)A1;
    float4 vb0 = *(const float4*)B0;
    float4 vb1 = *(const float4*)B1;
    FIN_STORE(0);
    va0 = *(const float4*)(A0 + 16);
    va1 = *(const float4*)(A1 + 16);
    vb0 = *(const float4*)(B0 + (size_t)16 * LDIM);
    vb1 = *(const float4*)(B1 + (size_t)16 * LDIM);
    __syncthreads();

    for (int kt = 0; kt < 16; kt++) {
        const int p = kt & 1;
        if (kt + 1 < 16) {
            FIN_STORE(p ^ 1);
            if (kt + 2 < 16) {
                va0 = *(const float4*)(A0 + (kt + 2) * 16);
                va1 = *(const float4*)(A1 + (kt + 2) * 16);
                vb0 = *(const float4*)(B0 + (size_t)(kt + 2) * 16 * LDIM);
                vb1 = *(const float4*)(B1 + (size_t)(kt + 2) * 16 * LDIM);
            }
        }
#pragma unroll
        for (int s = 0; s < 2; s++) {
            const int k0 = s * 8;
            const int sl = s * 4 + tg;
            uint32_t ah[4][4], bh[4][2];
#pragma unroll
            for (int mt = 0; mt < 4; mt++) {
                const int r = m0 + mt * 16 + g;
                float2 p0 = Ap[p][r][sl];
                float2 p1 = Ap[p][r + 8][sl];
                ah[mt][0] = __float_as_uint(p0.x);
                ah[mt][1] = __float_as_uint(p1.x);
                ah[mt][2] = __float_as_uint(p0.y);
                ah[mt][3] = __float_as_uint(p1.y);
            }
#pragma unroll
            for (int nt = 0; nt < 4; nt++) {
                const int cn = n0 + nt * 8 + g;
                bh[nt][0] = __float_as_uint(Bs[p][k0 + tg][cn]);
                bh[nt][1] = __float_as_uint(Bs[p][k0 + tg + 4][cn]);
            }
#pragma unroll
            for (int mt = 0; mt < 4; mt++)
#pragma unroll
                for (int nt = 0; nt < 4; nt++)
                    MMA_TF32(acc[mt][nt], ah[mt], bh[nt]);
        }
        __syncthreads();
    }
#undef FIN_STORE

#pragma unroll
    for (int mt = 0; mt < 4; mt++)
#pragma unroll
        for (int nt = 0; nt < 4; nt++) {
            const int r = m0 + mt * 16 + g;
            const int c = n0 + nt * 8 + 2 * tg;
            float2 v0; v0.x = acc[mt][nt][0]; v0.y = acc[mt][nt][1];
            float2 v1; v1.x = acc[mt][nt][2]; v1.y = acc[mt][nt][3];
            *(float2*)(yb + (size_t)r * LDIM + c) = v0;
            *(float2*)(yb + (size_t)(r + 8) * LDIM + c) = v1;
        }
}

// ---------------------------------------------------------------------------
// Launch
// ---------------------------------------------------------------------------
extern "C" void kernel_launch(void* const* d_in, const int* in_sizes, int n_in,
                              void* d_out, int out_size) {
    const float *x = nullptr, *wq = nullptr, *wk = nullptr, *wv = nullptr;
    for (int i = 0; i < n_in; i++) {
        if (in_sizes[i] == BDIM * CDIM * LDIM) {
            x = (const float*)d_in[i];
        } else if (!wq) wq = (const float*)d_in[i];
        else if (!wk) wk = (const float*)d_in[i];
        else wv = (const float*)d_in[i];
    }
    float* y = (float*)d_out;

    gram_mma<<<dim3(3, NSPLIT, BDIM), 256>>>(x);
    gram_reduce<<<dim3(192, BDIM), 256>>>();
    sym_diag<<<dim3(10, 2, BDIM), 256>>>();
    gemm_h2_kernel<<<dim3(8, 4, BDIM), 256>>>(wk);
    gemm_attn_kernel<<<dim3(8, 4, BDIM), 256>>>(wq);
    softmax_kernel<<<dim3(16, BDIM), 256>>>();
    gemm_m_kernel<<<dim3(8, 4, BDIM), 256>>>(wv);
    final_mma<<<dim3(LDIM / 128, 2, BDIM), 256>>>(x, y);
}

// round 13
// speedup vs baseline: 1.6130x; 1.1132x over previous
#include <cuda_runtime.h>
#include <cstdint>
#include <math.h>

// Problem constants
#define BDIM 4
#define CDIM 256
#define LDIM 32768
#define NSTAGES 2048          // k16-stages per (batch, tile)

// Balanced persistent split: 8 diag combos x 22 pieces + 4 offdiag x 30 = 296
#define ND_PIECES 22
#define NO_PIECES 30
#define GRAM_BLOCKS 296
#define DIAG_BLOCKS (8 * ND_PIECES)   // 176

// ---------------------------------------------------------------------------
// Scratch (static device arrays)
// ---------------------------------------------------------------------------
__device__ float gP[GRAM_BLOCKS * 128 * 128];        // partial Gram tiles (19.4MB)
__device__ float gG[BDIM * CDIM * CDIM];             // G = x x^T
__device__ float gH2[BDIM * CDIM * CDIM];            // H2 = W_K * G
__device__ float gAm[BDIM * CDIM * CDIM];            // logits -> softmax
__device__ float gM[BDIM * CDIM * CDIM];             // M = A * W_V

// ---------------------------------------------------------------------------
// mma.sync tf32 + bf16 (sm_80+ PTX — works under compute_100)
// ---------------------------------------------------------------------------
__device__ __forceinline__ float tf32_hi(float v) {
    uint32_t u;
    asm("cvt.rna.tf32.f32 %0, %1;" : "=r"(u) : "f"(v));
    return __uint_as_float(u);
}

// pack (v0 -> low half, v1 -> high half) as bf16x2
__device__ __forceinline__ uint32_t bf16pair(float v0, float v1) {
    uint32_t r;
    asm("cvt.rn.bf16x2.f32 %0, %1, %2;" : "=r"(r) : "f"(v1), "f"(v0));
    return r;
}

#define MMA_TF32(c, a, b)                                                     \
    asm volatile("mma.sync.aligned.m16n8k8.row.col.f32.tf32.tf32.f32 "        \
                 "{%0,%1,%2,%3}, {%4,%5,%6,%7}, {%8,%9}, {%0,%1,%2,%3};"      \
                 : "+f"((c)[0]), "+f"((c)[1]), "+f"((c)[2]), "+f"((c)[3])     \
                 : "r"((a)[0]), "r"((a)[1]), "r"((a)[2]), "r"((a)[3]),        \
                   "r"((b)[0]), "r"((b)[1]))

#define MMA_BF16(c, a, b)                                                     \
    asm volatile("mma.sync.aligned.m16n8k16.row.col.f32.bf16.bf16.f32 "       \
                 "{%0,%1,%2,%3}, {%4,%5,%6,%7}, {%8,%9}, {%0,%1,%2,%3};"      \
                 : "+f"((c)[0]), "+f"((c)[1]), "+f"((c)[2]), "+f"((c)[3])     \
                 : "r"((a)[0]), "r"((a)[1]), "r"((a)[2]), "r"((a)[3]),        \
                   "r"((b)[0]), "r"((b)[1]))

// ---------------------------------------------------------------------------
// Phase 1: Gram partials — R12 math (tf32 hi*hi + bf16 cross terms) with a
// WAVE-BALANCED persistent mapping: exactly 296 blocks (= 148 SMs x occ 2),
// diag combos get 22 k-pieces, off-diag get 30 (work-proportional: diag does
// 3 instr-units/stage vs 4). Per-block work spread < 2%.
//   u < 176:  diag:  cd = u/22, piece = u%22, t = (cd&1)?2:0, b = cd>>1
//   u >= 176: off:   b = (u-176)/30, piece = (u-176)%30, t = 1
// Piece stages: balanced division of 2048 (93/94 diag, 68/69 off-diag).
// ---------------------------------------------------------------------------
__global__ void __launch_bounds__(256, 2) gram_mma(const float* __restrict__ x) {
    __shared__ float    HsA[128][20];
    __shared__ uint32_t HpA[128][12], LpA[128][12];
    __shared__ float    HsB[128][20];
    __shared__ uint32_t HpB[128][12], LpB[128][12];

    const int u = blockIdx.x;
    int b, t, piece, q, r;
    if (u < DIAG_BLOCKS) {
        const int cd = u / ND_PIECES;
        piece = u - cd * ND_PIECES;
        t = (cd & 1) ? 2 : 0;
        b = cd >> 1;
        q = NSTAGES / ND_PIECES;              // 93
        r = NSTAGES - q * ND_PIECES;          // 2
    } else {
        const int v = u - DIAG_BLOCKS;
        b = v / NO_PIECES;
        piece = v - b * NO_PIECES;
        t = 1;
        q = NSTAGES / NO_PIECES;              // 68
        r = NSTAGES - q * NO_PIECES;          // 8
    }
    const int start = piece * q + (piece < r ? piece : r);
    const int ns = q + (piece < r ? 1 : 0);
    const bool diag = (t != 1);
    const int ti = (t == 2) ? 1 : 0;
    const int tj = (t == 0) ? 0 : 1;
    const float* Ab = x + ((size_t)b * CDIM + ti * 128) * LDIM + (size_t)start * 16;
    const float* Bb = x + ((size_t)b * CDIM + tj * 128) * LDIM + (size_t)start * 16;

    const int tid = threadIdx.x;
    const int warp = tid >> 5, lane = tid & 31;
    const int g = lane >> 2, tg = lane & 3;
    const int m0 = (warp >> 2) * 64, n0 = (warp & 3) * 32;
    const int lrow = tid >> 2, lkq = (tid & 3) * 4;
    const int pk = lkq >> 1;                      // bf16 pair index base

    float acc[4][4][4];
#pragma unroll
    for (int i = 0; i < 4; i++)
#pragma unroll
        for (int j = 0; j < 4; j++)
#pragma unroll
            for (int k = 0; k < 4; k++) acc[i][j][k] = 0.f;

    const float* A0 = Ab + (size_t)lrow * LDIM + lkq;
    const float* A1 = A0 + (size_t)64 * LDIM;
    const float* B0 = Bb + (size_t)lrow * LDIM + lkq;
    const float* B1 = B0 + (size_t)64 * LDIM;

    float4 va0 = *(const float4*)A0;
    float4 va1 = *(const float4*)A1;
    float4 vb0, vb1;
    if (!diag) { vb0 = *(const float4*)B0; vb1 = *(const float4*)B1; }

#define GRAM_STORE_ROW(Hs, Hp, Lp, row, v)                                     \
    do {                                                                       \
        float h0 = tf32_hi((v).x), h1 = tf32_hi((v).y);                        \
        float h2 = tf32_hi((v).z), h3 = tf32_hi((v).w);                        \
        Hs[row][lkq + 0] = h0; Hs[row][lkq + 1] = h1;                          \
        Hs[row][lkq + 2] = h2; Hs[row][lkq + 3] = h3;                          \
        Hp[row][pk]     = bf16pair(h0, h1);                                    \
        Hp[row][pk + 1] = bf16pair(h2, h3);                                    \
        Lp[row][pk]     = bf16pair((v).x - h0, (v).y - h1);                    \
        Lp[row][pk + 1] = bf16pair((v).z - h2, (v).w - h3);                    \
    } while (0)

    for (int kt = 0; kt < ns; kt++) {
        GRAM_STORE_ROW(HsA, HpA, LpA, lrow, va0);
        GRAM_STORE_ROW(HsA, HpA, LpA, lrow + 64, va1);
        if (!diag) {
            GRAM_STORE_ROW(HsB, HpB, LpB, lrow, vb0);
            GRAM_STORE_ROW(HsB, HpB, LpB, lrow + 64, vb1);
        }
        __syncthreads();
        if (kt + 1 < ns) {
            const int ko = (kt + 1) * 16;
            va0 = *(const float4*)(A0 + ko);
            va1 = *(const float4*)(A1 + ko);
            if (!diag) {
                vb0 = *(const float4*)(B0 + ko);
                vb1 = *(const float4*)(B1 + ko);
            }
        }

        // ---- bf16 cross terms ----
        {
            // pass 1: Ah * Bl^T  (diag: Bl = La)
            uint32_t a16[4][4], b16[4][2];
#pragma unroll
            for (int mt = 0; mt < 4; mt++) {
                const int rr = m0 + mt * 16 + g;
                a16[mt][0] = HpA[rr][tg];
                a16[mt][1] = HpA[rr + 8][tg];
                a16[mt][2] = HpA[rr][tg + 4];
                a16[mt][3] = HpA[rr + 8][tg + 4];
            }
#pragma unroll
            for (int nt = 0; nt < 4; nt++) {
                const int rn = n0 + nt * 8 + g;
                const uint32_t (*Lsrc)[12] = diag ? LpA : LpB;
                b16[nt][0] = Lsrc[rn][tg];
                b16[nt][1] = Lsrc[rn][tg + 4];
            }
#pragma unroll
            for (int mt = 0; mt < 4; mt++)
#pragma unroll
                for (int nt = 0; nt < 4; nt++)
                    MMA_BF16(acc[mt][nt], a16[mt], b16[nt]);
        }
        if (!diag) {
            // pass 2: Al * Bh^T
            uint32_t a16[4][4], b16[4][2];
#pragma unroll
            for (int mt = 0; mt < 4; mt++) {
                const int rr = m0 + mt * 16 + g;
                a16[mt][0] = LpA[rr][tg];
                a16[mt][1] = LpA[rr + 8][tg];
                a16[mt][2] = LpA[rr][tg + 4];
                a16[mt][3] = LpA[rr + 8][tg + 4];
            }
#pragma unroll
            for (int nt = 0; nt < 4; nt++) {
                const int rn = n0 + nt * 8 + g;
                b16[nt][0] = HpB[rn][tg];
                b16[nt][1] = HpB[rn][tg + 4];
            }
#pragma unroll
            for (int mt = 0; mt < 4; mt++)
#pragma unroll
                for (int nt = 0; nt < 4; nt++)
                    MMA_BF16(acc[mt][nt], a16[mt], b16[nt]);
        }

        // ---- tf32 hi*hi (k8 x2). Diag: A-side scaled by 0.5 ----
#pragma unroll
        for (int s = 0; s < 2; s++) {
            const int k0 = s * 8;
            uint32_t ah[4][4], bh[4][2];
            const float asc = diag ? 0.5f : 1.0f;
#pragma unroll
            for (int mt = 0; mt < 4; mt++) {
                const int rr = m0 + mt * 16 + g;
                ah[mt][0] = __float_as_uint(asc * HsA[rr][k0 + tg]);
                ah[mt][1] = __float_as_uint(asc * HsA[rr + 8][k0 + tg]);
                ah[mt][2] = __float_as_uint(asc * HsA[rr][k0 + tg + 4]);
                ah[mt][3] = __float_as_uint(asc * HsA[rr + 8][k0 + tg + 4]);
            }
#pragma unroll
            for (int nt = 0; nt < 4; nt++) {
                const int rn = n0 + nt * 8 + g;
                const float (*Hsrc)[20] = diag ? HsA : HsB;
                bh[nt][0] = __float_as_uint(Hsrc[rn][k0 + tg]);
                bh[nt][1] = __float_as_uint(Hsrc[rn][k0 + tg + 4]);
            }
#pragma unroll
            for (int mt = 0; mt < 4; mt++)
#pragma unroll
                for (int nt = 0; nt < 4; nt++)
                    MMA_TF32(acc[mt][nt], ah[mt], bh[nt]);
        }
        __syncthreads();
    }
#undef GRAM_STORE_ROW

    float* Cp = gP + (size_t)u * 16384;
#pragma unroll
    for (int mt = 0; mt < 4; mt++)
#pragma unroll
        for (int nt = 0; nt < 4; nt++) {
            const int rr = m0 + mt * 16 + g;
            const int c = n0 + nt * 8 + 2 * tg;
            float2 v0; v0.x = acc[mt][nt][0]; v0.y = acc[mt][nt][1];
            float2 v1; v1.x = acc[mt][nt][2]; v1.y = acc[mt][nt][3];
            *(float2*)(Cp + (size_t)rr * 128 + c) = v0;
            *(float2*)(Cp + (size_t)(rr + 8) * 128 + c) = v1;
        }
}

// Reduce partials over pieces into G. grid (64, 12): y = combo.
// combo < 8: diag (t = (combo&1)?2:0, b = combo>>1), slots [combo*22, +22)
// combo >= 8: off-diag b = combo-8, slots [176 + b*30, +30)
__global__ void gram_reduce() {
    const int e = blockIdx.x * 256 + threadIdx.x;   // 0..16383
    const int cy = blockIdx.y;
    const int i = e >> 7, j = e & 127;
    int base, np, t, b;
    if (cy < 8) {
        base = cy * ND_PIECES; np = ND_PIECES;
        t = (cy & 1) ? 2 : 0;  b = cy >> 1;
    } else {
        b = cy - 8;
        base = DIAG_BLOCKS + b * NO_PIECES; np = NO_PIECES;
        t = 1;
    }
    const float* p = gP + (size_t)base * 16384 + e;
    float sum = 0.f;
    for (int s = 0; s < np; s++) sum += p[(size_t)s * 16384];
    float* Gb = gG + (size_t)b * 65536;
    if (t == 0) {
        Gb[(size_t)i * 256 + j] = sum;
    } else if (t == 2) {
        Gb[(size_t)(128 + i) * 256 + (128 + j)] = sum;
    } else {
        Gb[(size_t)i * 256 + (128 + j)] = sum;
        Gb[(size_t)(128 + j) * 256 + i] = sum;
    }
}

// Symmetrize diag blocks in place: G[p][q] = Graw[p][q] + Graw[q][p].
__global__ void sym_diag() {
    const int pu[10] = {0, 0, 0, 0, 1, 1, 1, 2, 2, 3};
    const int pv[10] = {0, 1, 2, 3, 1, 2, 3, 2, 3, 3};
    const int pr = blockIdx.x, dblk = blockIdx.y, b = blockIdx.z;
    const int u = pu[pr], v = pv[pr];
    const int base = dblk * 128;
    float* Gb = gG + (size_t)b * 65536;
    __shared__ float Ta[32][33], Tb[32][33];
    const int r = threadIdx.x >> 3, c4 = (threadIdx.x & 7) * 4;
    const int ar = base + u * 32, ac = base + v * 32;
    const int br = base + v * 32, bc = base + u * 32;
    float4 a = *(const float4*)(Gb + (size_t)(ar + r) * 256 + ac + c4);
    float4 bq = *(const float4*)(Gb + (size_t)(br + r) * 256 + bc + c4);
#pragma unroll
    for (int j = 0; j < 4; j++) {
        Ta[r][c4 + j] = ((const float*)&a)[j];
        Tb[r][c4 + j] = ((const float*)&bq)[j];
    }
    __syncthreads();
    float4 o1, o2;
#pragma unroll
    for (int j = 0; j < 4; j++) {
        ((float*)&o1)[j] = Ta[r][c4 + j] + Tb[c4 + j][r];
        ((float*)&o2)[j] = Tb[r][c4 + j] + Ta[c4 + j][r];
    }
    *(float4*)(Gb + (size_t)(ar + r) * 256 + ac + c4) = o1;
    if (u != v)
        *(float4*)(Gb + (size_t)(br + r) * 256 + bc + c4) = o2;
}

// ---------------------------------------------------------------------------
// 32x64 SGEMM tiles for the middle GEMMs, DOUBLE-BUFFERED (R10/R11-proven).
// grid 8x4xB = 128 blocks.
// ---------------------------------------------------------------------------
struct Smem3264 {
    float As[2][16][36];
    float Bs[2][16][68];
};

// NT: C[m][n] = sum_k A[m][k] * B[n][k]
__device__ __forceinline__ void gemm_nt_3264(Smem3264& s,
                                             const float* __restrict__ A,
                                             const float* __restrict__ B,
                                             float* __restrict__ C) {
    const int tid = threadIdx.x;
    const int row = tid >> 2, kq = (tid & 3) * 4;
    const int tx = tid & 15, ty = tid >> 4;
    const int n0 = tx * 4, m0 = ty * 2;
    float acc[2][4] = {};
    float4 a, bv;

#define NT_STORE(st)                                                           \
    do {                                                                       \
        if (tid < 128) {                                                       \
            _Pragma("unroll") for (int j = 0; j < 4; j++)                      \
                s.As[st][kq + j][row] = ((const float*)&a)[j];                 \
        }                                                                      \
        _Pragma("unroll") for (int j = 0; j < 4; j++)                          \
            s.Bs[st][kq + j][row] = ((const float*)&bv)[j];                    \
    } while (0)

    if (tid < 128) a = *(const float4*)(A + (size_t)row * 256 + kq);
    bv = *(const float4*)(B + (size_t)row * 256 + kq);
    NT_STORE(0);
    if (tid < 128) a = *(const float4*)(A + (size_t)row * 256 + 16 + kq);
    bv = *(const float4*)(B + (size_t)row * 256 + 16 + kq);
    __syncthreads();

    for (int kt = 0; kt < 16; kt++) {
        const int p = kt & 1;
        if (kt + 1 < 16) {
            NT_STORE(p ^ 1);
            if (kt + 2 < 16) {
                if (tid < 128)
                    a = *(const float4*)(A + (size_t)row * 256 + (kt + 2) * 16 + kq);
                bv = *(const float4*)(B + (size_t)row * 256 + (kt + 2) * 16 + kq);
            }
        }
#pragma unroll
        for (int kk = 0; kk < 16; kk++) {
            const float av0 = s.As[p][kk][m0];
            const float av1 = s.As[p][kk][m0 + 1];
#pragma unroll
            for (int j = 0; j < 4; j++) {
                const float bb = s.Bs[p][kk][n0 + j];
                acc[0][j] += av0 * bb;
                acc[1][j] += av1 * bb;
            }
        }
        __syncthreads();
    }
#undef NT_STORE
#pragma unroll
    for (int i = 0; i < 2; i++) {
        float4 v;
        v.x = acc[i][0]; v.y = acc[i][1]; v.z = acc[i][2]; v.w = acc[i][3];
        *(float4*)(C + (size_t)(m0 + i) * 256 + n0) = v;
    }
}

// NN: C[m][n] = sum_k A[m][k] * B[k][n]  (B row-major [k][n], ldb=256)
__device__ __forceinline__ void gemm_nn_3264(Smem3264& s,
                                             const float* __restrict__ A,
                                             const float* __restrict__ B,
                                             float* __restrict__ C) {
    const int tid = threadIdx.x;
    const int row = tid >> 2, kq = (tid & 3) * 4;
    const int kr = tid >> 4, cq = (tid & 15) * 4;
    const int tx = tid & 15, ty = tid >> 4;
    const int n0 = tx * 4, m0 = ty * 2;
    float acc[2][4] = {};
    float4 a, bv;

#define NN_STORE(st)                                                           \
    do {                                                                       \
        if (tid < 128) {                                                       \
            _Pragma("unroll") for (int j = 0; j < 4; j++)                      \
                s.As[st][kq + j][row] = ((const float*)&a)[j];                 \
        }                                                                      \
        _Pragma("unroll") for (int j = 0; j < 4; j++)                          \
            s.Bs[st][kr][cq + j] = ((const float*)&bv)[j];                     \
    } while (0)

    if (tid < 128) a = *(const float4*)(A + (size_t)row * 256 + kq);
    bv = *(const float4*)(B + (size_t)kr * 256 + cq);
    NN_STORE(0);
    if (tid < 128) a = *(const float4*)(A + (size_t)row * 256 + 16 + kq);
    bv = *(const float4*)(B + (size_t)(16 + kr) * 256 + cq);
    __syncthreads();

    for (int kt = 0; kt < 16; kt++) {
        const int p = kt & 1;
        if (kt + 1 < 16) {
            NN_STORE(p ^ 1);
            if (kt + 2 < 16) {
                if (tid < 128)
                    a = *(const float4*)(A + (size_t)row * 256 + (kt + 2) * 16 + kq);
                bv = *(const float4*)(B + (size_t)((kt + 2) * 16 + kr) * 256 + cq);
            }
        }
#pragma unroll
        for (int kk = 0; kk < 16; kk++) {
            const float av0 = s.As[p][kk][m0];
            const float av1 = s.As[p][kk][m0 + 1];
#pragma unroll
            for (int j = 0; j < 4; j++) {
                const float bb = s.Bs[p][kk][n0 + j];
                acc[0][j] += av0 * bb;
                acc[1][j] += av1 * bb;
            }
        }
        __syncthreads();
    }
#undef NN_STORE
#pragma unroll
    for (int i = 0; i < 2; i++) {
        float4 v;
        v.x = acc[i][0]; v.y = acc[i][1]; v.z = acc[i][2]; v.w = acc[i][3];
        *(float4*)(C + (size_t)(m0 + i) * 256 + n0) = v;
    }
}

__global__ void __launch_bounds__(256) gemm_h2_kernel(const float* __restrict__ wk) {
    __shared__ Smem3264 s;
    const int bx = blockIdx.x, by = blockIdx.y, b = blockIdx.z;
    gemm_nt_3264(s, wk + (size_t)bx * 32 * 256,
                 gG + (size_t)b * 65536 + (size_t)by * 64 * 256,
                 gH2 + (size_t)b * 65536 + (size_t)bx * 32 * 256 + by * 64);
}
__global__ void __launch_bounds__(256) gemm_attn_kernel(const float* __restrict__ wq) {
    __shared__ Smem3264 s;
    const int bx = blockIdx.x, by = blockIdx.y, b = blockIdx.z;
    gemm_nt_3264(s, wq + (size_t)bx * 32 * 256,
                 gH2 + (size_t)b * 65536 + (size_t)by * 64 * 256,
                 gAm + (size_t)b * 65536 + (size_t)bx * 32 * 256 + by * 64);
}
__global__ void __launch_bounds__(256) gemm_m_kernel(const float* __restrict__ wv) {
    __shared__ Smem3264 s;
    const int bx = blockIdx.x, by = blockIdx.y, b = blockIdx.z;
    gemm_nn_3264(s, gAm + (size_t)b * 65536 + (size_t)bx * 32 * 256,
                 wv + by * 64,
                 gM + (size_t)b * 65536 + (size_t)bx * 32 * 256 + by * 64);
}

// ---------------------------------------------------------------------------
// Softmax over q (axis=-2), grid (16, B): 16 cols/block, 16 q per thread.
// ---------------------------------------------------------------------------
__global__ void __launch_bounds__(256) softmax_kernel() {
    const int b = blockIdx.y;
    const int tc = threadIdx.x & 15, tq = threadIdx.x >> 4;
    const int col = blockIdx.x * 16 + tc;
    float* Ab = gAm + (size_t)b * 65536;

    float v[16];
    float m = -3.0e38f;
#pragma unroll
    for (int qi = 0; qi < 16; qi++) {
        v[qi] = Ab[(size_t)(tq + qi * 16) * 256 + col];
        m = fmaxf(m, v[qi]);
    }
    __shared__ float red[16][16];
    red[tq][tc] = m;
    __syncthreads();
    float mm = red[0][tc];
#pragma unroll
    for (int r = 1; r < 16; r++) mm = fmaxf(mm, red[r][tc]);
    __syncthreads();
    float ssum = 0.f;
#pragma unroll
    for (int qi = 0; qi < 16; qi++) {
        v[qi] = expf(v[qi] - mm);
        ssum += v[qi];
    }
    red[tq][tc] = ssum;
    __syncthreads();
    float tot = 0.f;
#pragma unroll
    for (int r = 0; r < 16; r++) tot += red[r][tc];
    const float inv = 1.f / tot;
#pragma unroll
    for (int qi = 0; qi < 16; qi++)
        Ab[(size_t)(tq + qi * 16) * 256 + col] = v[qi] * inv;
}

// ---------------------------------------------------------------------------
// Phase 5: y[b] = M[b] @ x[b] via mma.sync, 1x TF32, 2-stage double buffer.
// ---------------------------------------------------------------------------
__global__ void __launch_bounds__(256, 2) final_mma(const float* __restrict__ x,
                                                    float* __restrict__ y) {
    __shared__ float2 Ap[2][128][10];
    __shared__ float Bs[2][16][136];

    const int lx = blockIdx.x, qy = blockIdx.y, b = blockIdx.z;
    const float* Mb = gM + (size_t)b * 65536 + (size_t)qy * 128 * 256;
    const float* xb = x + (size_t)b * CDIM * LDIM + (size_t)lx * 128;
    float* yb = y + ((size_t)b * CDIM + (size_t)qy * 128) * LDIM + (size_t)lx * 128;

    const int tid = threadIdx.x;
    const int warp = tid >> 5, lane = tid & 31;
    const int g = lane >> 2, tg = lane & 3;
    const int m0 = (warp >> 2) * 64, n0 = (warp & 3) * 32;
    const int lrow = tid >> 2, lkq = (tid & 3) * 4;
    const int brow = tid >> 5, blq = (tid & 31) * 4;
    const int aslot0 = (lkq >= 8) ? 4 : 0;
    const int acomp = ((lkq >> 2) & 1);

    float acc[4][4][4];
#pragma unroll
    for (int i = 0; i < 4; i++)
#pragma unroll
        for (int j = 0; j < 4; j++)
#pragma unroll
            for (int k = 0; k < 4; k++) acc[i][j][k] = 0.f;

    const float* A0 = Mb + (size_t)lrow * 256 + lkq;
    const float* A1 = A0 + (size_t)64 * 256;
    const float* B0 = xb + (size_t)brow * LDIM + blq;
    const float* B1 = B0 + (size_t)8 * LDIM;

#define FIN_STORE(st)                                                          \
    do {                                                                       \
        float* a0p = (float*)&Ap[st][lrow][aslot0];                            \
        float* a1p = (float*)&Ap[st][lrow + 64][aslot0];                       \
        _Pragma("unroll") for (int j = 0; j < 4; j++) {                        \
            a0p[2 * j + acomp] = tf32_hi(((const float*)&va0)[j]);             \
            a1p[2 * j + acomp] = tf32_hi(((const float*)&va1)[j]);             \
            Bs[st][brow][blq + j] = tf32_hi(((const float*)&vb0)[j]);          \
            Bs[st][brow + 8][blq + j] = tf32_hi(((const float*)&vb1)[j]);      \
        }                                                                      \
    } while (0)

    float4 va0 = *(const float4*)A0;
    float4 va1 = *(const float4*)A1;
    float4 vb0 = *(const float4*)B0;
    float4 vb1 = *(const float4*)B1;
    FIN_STORE(0);
    va0 = *(const float4*)(A0 + 16);
    va1 = *(const float4*)(A1 + 16);
    vb0 = *(const float4*)(B0 + (size_t)16 * LDIM);
    vb1 = *(const float4*)(B1 + (size_t)16 * LDIM);
    __syncthreads();

    for (int kt = 0; kt < 16; kt++) {
        const int p = kt & 1;
        if (kt + 1 < 16) {
            FIN_STORE(p ^ 1);
            if (kt + 2 < 16) {
                va0 = *(const float4*)(A0 + (kt + 2) * 16);
                va1 = *(const float4*)(A1 + (kt + 2) * 16);
                vb0 = *(const float4*)(B0 + (size_t)(kt + 2) * 16 * LDIM);
                vb1 = *(const float4*)(B1 + (size_t)(kt + 2) * 16 * LDIM);
            }
        }
#pragma unroll
        for (int s = 0; s < 2; s++) {
            const int k0 = s * 8;
            const int sl = s * 4 + tg;
            uint32_t ah[4][4], bh[4][2];
#pragma unroll
            for (int mt = 0; mt < 4; mt++) {
                const int r = m0 + mt * 16 + g;
                float2 p0 = Ap[p][r][sl];
                float2 p1 = Ap[p][r + 8][sl];
                ah[mt][0] = __float_as_uint(p0.x);
                ah[mt][1] = __float_as_uint(p1.x);
                ah[mt][2] = __float_as_uint(p0.y);
                ah[mt][3] = __float_as_uint(p1.y);
            }
#pragma unroll
            for (int nt = 0; nt < 4; nt++) {
                const int cn = n0 + nt * 8 + g;
                bh[nt][0] = __float_as_uint(Bs[p][k0 + tg][cn]);
                bh[nt][1] = __float_as_uint(Bs[p][k0 + tg + 4][cn]);
            }
#pragma unroll
            for (int mt = 0; mt < 4; mt++)
#pragma unroll
                for (int nt = 0; nt < 4; nt++)
                    MMA_TF32(acc[mt][nt], ah[mt], bh[nt]);
        }
        __syncthreads();
    }
#undef FIN_STORE

#pragma unroll
    for (int mt = 0; mt < 4; mt++)
#pragma unroll
        for (int nt = 0; nt < 4; nt++) {
            const int r = m0 + mt * 16 + g;
            const int c = n0 + nt * 8 + 2 * tg;
            float2 v0; v0.x = acc[mt][nt][0]; v0.y = acc[mt][nt][1];
            float2 v1; v1.x = acc[mt][nt][2]; v1.y = acc[mt][nt][3];
            *(float2*)(yb + (size_t)r * LDIM + c) = v0;
            *(float2*)(yb + (size_t)(r + 8) * LDIM + c) = v1;
        }
}

// ---------------------------------------------------------------------------
// Launch
// ---------------------------------------------------------------------------
extern "C" void kernel_launch(void* const* d_in, const int* in_sizes, int n_in,
                              void* d_out, int out_size) {
    const float *x = nullptr, *wq = nullptr, *wk = nullptr, *wv = nullptr;
    for (int i = 0; i < n_in; i++) {
        if (in_sizes[i] == BDIM * CDIM * LDIM) {
            x = (const float*)d_in[i];
        } else if (!wq) wq = (const float*)d_in[i];
        else if (!wk) wk = (const float*)d_in[i];
        else wv = (const float*)d_in[i];
    }
    float* y = (float*)d_out;

    gram_mma<<<GRAM_BLOCKS, 256>>>(x);
    gram_reduce<<<dim3(64, 12), 256>>>();
    sym_diag<<<dim3(10, 2, BDIM), 256>>>();
    gemm_h2_kernel<<<dim3(8, 4, BDIM), 256>>>(wk);
    gemm_attn_kernel<<<dim3(8, 4, BDIM), 256>>>(wq);
    softmax_kernel<<<dim3(16, BDIM), 256>>>();
    gemm_m_kernel<<<dim3(8, 4, BDIM), 256>>>(wv);
    final_mma<<<dim3(LDIM / 128, 2, BDIM), 256>>>(x, y);
}